// round 15
// baseline (speedup 1.0000x reference)
#include <cuda_runtime.h>
#include <cuda_bf16.h>
#include <math.h>
#include <stdint.h>

#define Bb 2
#define Cc 512
#define Tt 16
#define NN 1024
#define HEADS 8
#define Dd 64
#define BT 32
#define C3 1536

typedef __nv_bfloat16 bf16;
typedef long long ll;

// ---------------- scratch (device globals) ----------------
__device__ __align__(16) bf16  g_wsqkv_t[Cc * C3];   // Wt[k][o]
__device__ __align__(16) bf16  g_wsout_c[Cc * Cc];   // W_sout[o][c] direct
__device__ __align__(16) bf16  g_wtqkv_t[Cc * C3];   // W_tqkv^T [o][p]
__device__ __align__(16) bf16  g_wtout_t[Cc * Cc];
__device__ __align__(16) bf16  g_wcomb[Cc * C3];     // (W_tqkv W_sout)^T [c][p]
__device__ __align__(16) float g_bcomb[C3];          // W_tqkv b_sout
__device__ __align__(16) bf16  g_xbf[Bb * Cc * Tt * NN];
__device__ __align__(16) bf16  g_sqkv[BT * C3 * NN];
__device__ __align__(16) bf16  g_ctx_ed[BT * HEADS * Dd * Dd];
__device__ __align__(16) bf16  g_sattn_bf[BT * Cc * NN];       // [bt][c][n]
__device__ __align__(16) bf16  g_tqkv[Bb * C3 * Tt * NN];
__device__ __align__(16) bf16  g_tout_bf[Bb * Cc * Tt * NN];

// ---------------- helpers ----------------
__device__ __forceinline__ uint32_t smem_u32(const void* p) {
    uint32_t a;
    asm("{ .reg .u64 t; cvta.to.shared.u64 t, %1; cvt.u32.u64 %0, t; }" : "=r"(a) : "l"(p));
    return a;
}
#define CP_ASYNC(dst, src) asm volatile("cp.async.cg.shared.global [%0],[%1],16;\n" :: "r"(dst), "l"(src) : "memory")
#define CP_COMMIT()        asm volatile("cp.async.commit_group;\n" ::: "memory")
#define CP_WAIT0()         asm volatile("cp.async.wait_group 0;\n" ::: "memory")
#define CP_WAIT1()         asm volatile("cp.async.wait_group 1;\n" ::: "memory")

#define LDSM_X4(r0,r1,r2,r3,addr) \
    asm volatile("ldmatrix.sync.aligned.m8n8.x4.shared.b16 {%0,%1,%2,%3},[%4];" \
                 : "=r"(r0),"=r"(r1),"=r"(r2),"=r"(r3) : "r"(addr))
#define LDSM_X4T(r0,r1,r2,r3,addr) \
    asm volatile("ldmatrix.sync.aligned.m8n8.x4.trans.shared.b16 {%0,%1,%2,%3},[%4];" \
                 : "=r"(r0),"=r"(r1),"=r"(r2),"=r"(r3) : "r"(addr))
#define LDSM_X2T(r0,r1,addr) \
    asm volatile("ldmatrix.sync.aligned.m8n8.x2.trans.shared.b16 {%0,%1},[%2];" \
                 : "=r"(r0),"=r"(r1) : "r"(addr))
#define MMA16816(d0,d1,d2,d3,a0,a1,a2,a3,b0,b1) \
    asm volatile("mma.sync.aligned.m16n8k16.row.col.f32.bf16.bf16.f32 " \
                 "{%0,%1,%2,%3},{%4,%5,%6,%7},{%8,%9},{%0,%1,%2,%3};" \
                 : "+f"(d0),"+f"(d1),"+f"(d2),"+f"(d3) \
                 : "r"(a0),"r"(a1),"r"(a2),"r"(a3),"r"(b0),"r"(b1))

// ---------------- merged prep: f2b(x) + weight conversions + bcomb ----------------
#define F2B_BLOCKS  16384
#define CONV_BLOCKS 8192
#define PREP_BLOCKS (F2B_BLOCKS + CONV_BLOCKS + 192)

__global__ __launch_bounds__(256) void prep_all(
    const float* __restrict__ x,
    const float* __restrict__ w1, const float* __restrict__ w2,
    const float* __restrict__ w3, const float* __restrict__ w4,
    const float* __restrict__ b_sout,
    bf16* __restrict__ xbf,
    bf16* __restrict__ o1, bf16* __restrict__ o2,
    bf16* __restrict__ o3, bf16* __restrict__ o4,
    float* __restrict__ bcomb)
{
    int blk = blockIdx.x;
    int tid = threadIdx.x;
    if (blk < F2B_BLOCKS) {
        int i = (blk * 256 + tid) * 4;
        float4 v = *(const float4*)(x + i);
        __nv_bfloat162 p0 = __floats2bfloat162_rn(v.x, v.y);
        __nv_bfloat162 p1 = __floats2bfloat162_rn(v.z, v.w);
        uint2 u;
        u.x = *(uint32_t*)&p0;
        u.y = *(uint32_t*)&p1;
        *(uint2*)(xbf + i) = u;
    } else if (blk < F2B_BLOCKS + CONV_BLOCKS) {
        const int N1 = C3 * Cc, N2 = Cc * Cc;
        int idx = (blk - F2B_BLOCKS) * 256 + tid;
        if (idx < N1) {
            int o = idx % C3, k = idx / C3;
            o1[idx] = __float2bfloat16(w1[(ll)o * Cc + k]);
        } else if (idx < N1 + N2) {
            int rem = idx - N1;
            o2[rem] = __float2bfloat16(w2[rem]);
        } else if (idx < 2 * N1 + N2) {
            int rem = idx - N1 - N2;
            int o = rem % C3, k = rem / C3;
            o3[rem] = __float2bfloat16(w3[(ll)o * Cc + k]);
        } else {
            int rem = idx - 2 * N1 - N2;
            int o = rem % Cc, k = rem / Cc;
            o4[rem] = __float2bfloat16(w4[(ll)o * Cc + k]);
        }
    } else {
        int p = (blk - F2B_BLOCKS - CONV_BLOCKS) * 8 + (tid >> 5);
        int lane = tid & 31;
        if (p >= C3) return;
        const float* wr = w3 + (ll)p * Cc;
        float s = 0.f;
        for (int o = lane; o < Cc; o += 32) s += wr[o] * b_sout[o];
        #pragma unroll
        for (int off = 16; off; off >>= 1) s += __shfl_xor_sync(0xffffffffu, s, off);
        if (lane == 0) bcomb[p] = s;
    }
}

// ---------------- bf16 tensor-core GEMM (128x128x32, 3-stage, optional fused q-softmax) ----------------
__global__ __launch_bounds__(256, 2) void gemm_bf16(
    const bf16* __restrict__ Wt,   // [K][ldA]
    const bf16* __restrict__ X,
    float* __restrict__ Cf,
    bf16* __restrict__ Cb,
    const float* __restrict__ bias,
    const float* __restrict__ res,
    int K, int ldA, int gDiv, int qsmax,
    ll xOuter, ll xInner, ll xRow,
    ll cOuter, ll cInner, ll cRow)
{
    __shared__ bf16 As[3][32][128];
    __shared__ bf16 Bs[3][32][128];

    int g = blockIdx.z;
    ll gq = g / gDiv, gr = g % gDiv;
    const bf16* Xb = X + gq * xOuter + gr * xInner;
    ll cbase = gq * cOuter + gr * cInner;

    int n0 = blockIdx.x * 128;
    int o0 = blockIdx.y * 128;

    int tid = threadIdx.x;
    int lane = tid & 31, warp = tid >> 5;
    int wm = warp >> 2, wn = warp & 3;

    uint32_t asb = smem_u32(&As[0][0][0]);
    uint32_t bsb = smem_u32(&Bs[0][0][0]);

    float acc[4][4][4];
    #pragma unroll
    for (int a = 0; a < 4; a++)
        #pragma unroll
        for (int b = 0; b < 4; b++)
            #pragma unroll
            for (int c = 0; c < 4; c++) acc[a][b][c] = 0.f;

    int nkt = K / 32;

    #define ISSUE_TILE(kt, buf) do {                                                     \
        int k0_ = (kt) * 32;                                                             \
        _Pragma("unroll")                                                                \
        for (int i_ = 0; i_ < 2; i_++) {                                                 \
            int idx_ = tid + 256 * i_;                                                   \
            int row_ = idx_ >> 4, ch_ = idx_ & 15;                                       \
            const bf16* sA = Wt + (ll)(k0_ + row_) * ldA + o0 + ch_ * 8;                 \
            uint32_t dA = asb + (buf) * 8192 + row_ * 256 + (((ch_) ^ (row_ & 7)) << 4); \
            CP_ASYNC(dA, sA);                                                            \
            const bf16* sB = Xb + (ll)(k0_ + row_) * xRow + n0 + ch_ * 8;                \
            uint32_t dB = bsb + (buf) * 8192 + row_ * 256 + (((ch_) ^ (row_ & 7)) << 4); \
            CP_ASYNC(dB, sB);                                                            \
        }                                                                                \
    } while (0)

    ISSUE_TILE(0, 0);
    CP_COMMIT();
    ISSUE_TILE(1, 1);
    CP_COMMIT();

    int r7 = lane & 7, sub = lane >> 3;
    int brow_lo = lane & 15;

    for (int kt = 0; kt < nkt; kt++) {
        CP_WAIT1();
        __syncthreads();
        if (kt + 2 < nkt) {
            int nb = (kt + 2) % 3;
            ISSUE_TILE(kt + 2, nb);
        }
        CP_COMMIT();
        int buf = kt % 3;
        uint32_t abase = asb + buf * 8192;
        uint32_t bbase = bsb + buf * 8192;

        #pragma unroll
        for (int ks = 0; ks < 2; ks++) {
            uint32_t af[4][4];
            uint32_t bf_[4][2];
            #pragma unroll
            for (int mt = 0; mt < 4; mt++) {
                int krow = ks * 16 + r7 + ((sub >> 1) << 3);
                int mcol = wm * 64 + mt * 16 + ((sub & 1) << 3);
                uint32_t addr = abase + krow * 256 + ((((mcol >> 3)) ^ (krow & 7)) << 4);
                LDSM_X4T(af[mt][0], af[mt][1], af[mt][2], af[mt][3], addr);
            }
            #pragma unroll
            for (int nt = 0; nt < 4; nt++) {
                int brow = ks * 16 + brow_lo;
                int ncol = wn * 32 + nt * 8;
                uint32_t addr = bbase + brow * 256 + ((((ncol >> 3)) ^ (brow & 7)) << 4);
                LDSM_X2T(bf_[nt][0], bf_[nt][1], addr);
            }
            #pragma unroll
            for (int mt = 0; mt < 4; mt++)
                #pragma unroll
                for (int nt = 0; nt < 4; nt++)
                    MMA16816(acc[mt][nt][0], acc[mt][nt][1], acc[mt][nt][2], acc[mt][nt][3],
                             af[mt][0], af[mt][1], af[mt][2], af[mt][3],
                             bf_[nt][0], bf_[nt][1]);
        }
    }

    if (qsmax && o0 < Cc) {
        #pragma unroll
        for (int nt = 0; nt < 4; nt++) {
            #pragma unroll
            for (int c = 0; c < 2; c++) {
                float m = -INFINITY;
                #pragma unroll
                for (int mt = 0; mt < 4; mt++) {
                    m = fmaxf(m, acc[mt][nt][c]);
                    m = fmaxf(m, acc[mt][nt][c + 2]);
                }
                m = fmaxf(m, __shfl_xor_sync(0xffffffffu, m, 4));
                m = fmaxf(m, __shfl_xor_sync(0xffffffffu, m, 8));
                m = fmaxf(m, __shfl_xor_sync(0xffffffffu, m, 16));
                float s = 0.f;
                #pragma unroll
                for (int mt = 0; mt < 4; mt++) {
                    acc[mt][nt][c]     = __expf(acc[mt][nt][c] - m);
                    acc[mt][nt][c + 2] = __expf(acc[mt][nt][c + 2] - m);
                    s += acc[mt][nt][c] + acc[mt][nt][c + 2];
                }
                s += __shfl_xor_sync(0xffffffffu, s, 4);
                s += __shfl_xor_sync(0xffffffffu, s, 8);
                s += __shfl_xor_sync(0xffffffffu, s, 16);
                float inv = 0.125f / s;
                #pragma unroll
                for (int mt = 0; mt < 4; mt++) {
                    acc[mt][nt][c]     *= inv;
                    acc[mt][nt][c + 2] *= inv;
                }
            }
        }
    }

    int g4 = lane >> 2, t4 = lane & 3;
    #pragma unroll
    for (int mt = 0; mt < 4; mt++) {
        #pragma unroll
        for (int nt = 0; nt < 4; nt++) {
            int orow = o0 + wm * 64 + mt * 16 + g4;
            int col  = n0 + wn * 32 + nt * 8 + t4 * 2;
            ll off0 = cbase + (ll)orow * cRow + col;
            ll off1 = off0 + 8 * cRow;
            float b0 = bias ? bias[orow] : 0.f;
            float b1 = bias ? bias[orow + 8] : 0.f;
            float* a = acc[mt][nt];
            if (Cb) {
                __nv_bfloat162 v0 = __floats2bfloat162_rn(a[0] + b0, a[1] + b0);
                __nv_bfloat162 v1 = __floats2bfloat162_rn(a[2] + b1, a[3] + b1);
                *reinterpret_cast<__nv_bfloat162*>(Cb + off0) = v0;
                *reinterpret_cast<__nv_bfloat162*>(Cb + off1) = v1;
            } else {
                float2 r0 = make_float2(0.f, 0.f), r1 = make_float2(0.f, 0.f);
                if (res) { r0 = *(const float2*)(res + off0); r1 = *(const float2*)(res + off1); }
                float2 o0v = make_float2(a[0] + b0 + r0.x, a[1] + b0 + r0.y);
                float2 o1v = make_float2(a[2] + b1 + r1.x, a[3] + b1 + r1.y);
                *(float2*)(Cf + off0) = o0v;
                *(float2*)(Cf + off1) = o1v;
            }
        }
    }
    #undef ISSUE_TILE
}

// ---------------- k softmax (over n, bf16 in/out, vectorized) ----------------
__global__ __launch_bounds__(256) void softmax_k(bf16* __restrict__ p)
{
    bf16* row = p + (ll)blockIdx.y * C3 * NN + (ll)(Cc + blockIdx.x) * NN;
    int tid = threadIdx.x;
    uint2 u = *(uint2*)(row + tid * 4);
    __nv_bfloat162 p0 = *(__nv_bfloat162*)&u.x;
    __nv_bfloat162 p1 = *(__nv_bfloat162*)&u.y;
    float v[4];
    v[0] = __bfloat162float(p0.x); v[1] = __bfloat162float(p0.y);
    v[2] = __bfloat162float(p1.x); v[3] = __bfloat162float(p1.y);
    float m = fmaxf(fmaxf(v[0], v[1]), fmaxf(v[2], v[3]));
    __shared__ float red[8];
    #pragma unroll
    for (int o = 16; o; o >>= 1) m = fmaxf(m, __shfl_xor_sync(0xffffffffu, m, o));
    if ((tid & 31) == 0) red[tid >> 5] = m;
    __syncthreads();
    m = red[0];
    #pragma unroll
    for (int wv = 1; wv < 8; wv++) m = fmaxf(m, red[wv]);
    __syncthreads();
    float s = 0.f;
    #pragma unroll
    for (int k = 0; k < 4; k++) { v[k] = __expf(v[k] - m); s += v[k]; }
    #pragma unroll
    for (int o = 16; o; o >>= 1) s += __shfl_xor_sync(0xffffffffu, s, o);
    if ((tid & 31) == 0) red[tid >> 5] = s;
    __syncthreads();
    s = 0.f;
    #pragma unroll
    for (int wv = 0; wv < 8; wv++) s += red[wv];
    float inv = 1.f / s;
    __nv_bfloat162 q0 = __floats2bfloat162_rn(v[0] * inv, v[1] * inv);
    __nv_bfloat162 q1 = __floats2bfloat162_rn(v[2] * inv, v[3] * inv);
    uint2 w;
    w.x = *(uint32_t*)&q0;
    w.y = *(uint32_t*)&q1;
    *(uint2*)(row + tid * 4) = w;
}

// ---------------- ctx (mma.sync): ctx_ed[e][d] = sum_n k[d][n] v[e][n] ----------------
__global__ __launch_bounds__(128) void ctx_mma(const bf16* __restrict__ qkv,
                                               bf16* __restrict__ ctx_ed)
{
    int h = blockIdx.x, bt = blockIdx.y;
    const bf16* kbase = qkv + (ll)bt * C3 * NN + (ll)(Cc + h * Dd) * NN;
    const bf16* vbase = qkv + (ll)bt * C3 * NN + (ll)(2 * Cc + h * Dd) * NN;

    __shared__ bf16 Ks[2][64 * 64];
    __shared__ bf16 Vs[2][64 * 64];
    uint32_t ksb = smem_u32(&Ks[0][0]);
    uint32_t vsb = smem_u32(&Vs[0][0]);

    int tid = threadIdx.x;
    int lane = tid & 31, warp = tid >> 5;
    int m0 = warp * 16;

    float acc[8][4] = {};

    #define CTX_ISSUE(c, buf) do {                                                  \
        _Pragma("unroll")                                                           \
        for (int i_ = 0; i_ < 8; i_++) {                                            \
            int idx_ = i_ * 128 + tid;                                              \
            int mat_ = idx_ >> 9;                                                   \
            int rem_ = idx_ & 511;                                                  \
            int row_ = rem_ >> 3, ch_ = rem_ & 7;                                   \
            const bf16* src_ = (mat_ ? vbase : kbase) + (ll)row_ * NN + (c) * 64 + ch_ * 8; \
            uint32_t dst_ = (mat_ ? vsb : ksb) + (buf) * 8192 + row_ * 128 + ((ch_ ^ (row_ & 7)) << 4); \
            CP_ASYNC(dst_, src_);                                                   \
        }                                                                           \
    } while (0)

    CTX_ISSUE(0, 0);
    CP_COMMIT();

    for (int c = 0; c < 16; c++) {
        CP_WAIT0();
        __syncthreads();
        if (c + 1 < 16) { CTX_ISSUE(c + 1, (c + 1) & 1); CP_COMMIT(); }
        int buf = c & 1;
        uint32_t ka = ksb + buf * 8192;
        uint32_t va = vsb + buf * 8192;
        #pragma unroll
        for (int ks = 0; ks < 4; ks++) {
            int k0 = ks * 16;
            uint32_t a0, a1, a2, a3;
            {
                int row = m0 + (lane & 15);
                int ch  = (k0 >> 3) + (lane >> 4);
                uint32_t addr = ka + row * 128 + ((ch ^ (row & 7)) << 4);
                LDSM_X4(a0, a1, a2, a3, addr);
            }
            #pragma unroll
            for (int nb = 0; nb < 4; nb++) {
                int row = nb * 16 + ((lane >> 4) << 3) + (lane & 7);
                int ch  = (k0 >> 3) + ((lane >> 3) & 1);
                uint32_t addr = va + row * 128 + ((ch ^ (row & 7)) << 4);
                uint32_t r0, r1, r2, r3;
                LDSM_X4(r0, r1, r2, r3, addr);
                MMA16816(acc[nb*2][0],   acc[nb*2][1],   acc[nb*2][2],   acc[nb*2][3],
                         a0, a1, a2, a3, r0, r1);
                MMA16816(acc[nb*2+1][0], acc[nb*2+1][1], acc[nb*2+1][2], acc[nb*2+1][3],
                         a0, a1, a2, a3, r2, r3);
            }
        }
    }
    #undef CTX_ISSUE

    bf16* cb = ctx_ed + ((ll)bt * HEADS + h) * (Dd * Dd);
    int g4 = lane >> 2, t4 = lane & 3;
    #pragma unroll
    for (int nt = 0; nt < 8; nt++) {
        int e0 = nt * 8 + t4 * 2;
        int d0 = m0 + g4;
        cb[(e0)     * Dd + d0]     = __float2bfloat16(acc[nt][0]);
        cb[(e0 + 1) * Dd + d0]     = __float2bfloat16(acc[nt][1]);
        cb[(e0)     * Dd + d0 + 8] = __float2bfloat16(acc[nt][2]);
        cb[(e0 + 1) * Dd + d0 + 8] = __float2bfloat16(acc[nt][3]);
    }
}

// ---------------- attn apply: out[e][n] -> sattn [bt][c][n] ----------------
__global__ __launch_bounds__(256) void attn_apply_mma(const bf16* __restrict__ ctx_ed,
                                                      const bf16* __restrict__ qkv,
                                                      bf16* __restrict__ out)
{
    int n0 = blockIdx.x * 256, h = blockIdx.y, bt = blockIdx.z;
    const bf16* cbase = ctx_ed + ((ll)bt * HEADS + h) * (Dd * Dd);
    const bf16* qbase = qkv + (ll)bt * C3 * NN + (ll)(h * Dd) * NN;

    __shared__ bf16 Asm[64 * 64];
    __shared__ bf16 Bsm[64 * 256];
    uint32_t asb = smem_u32(&Asm[0]);
    uint32_t bsb = smem_u32(&Bsm[0]);

    int tid = threadIdx.x;
    int lane = tid & 31, warp = tid >> 5;
    int wm = warp >> 2, wn = warp & 3;

    #pragma unroll
    for (int i = 0; i < 2; i++) {
        int idx = i * 256 + tid;
        int row = idx >> 3, ch = idx & 7;
        const bf16* src = cbase + row * Dd + ch * 8;
        uint32_t dst = asb + row * 128 + ((ch ^ (row & 7)) << 4);
        CP_ASYNC(dst, src);
    }
    #pragma unroll
    for (int i = 0; i < 8; i++) {
        int idx = i * 256 + tid;
        int row = idx >> 5, ch = idx & 31;
        const bf16* src = qbase + (ll)row * NN + n0 + ch * 8;
        uint32_t dst = bsb + row * 512 + ((ch ^ (row & 7)) << 4);
        CP_ASYNC(dst, src);
    }
    CP_COMMIT();
    CP_WAIT0();
    __syncthreads();

    float acc[2][8][4] = {};
    #pragma unroll
    for (int ks = 0; ks < 4; ks++) {
        int k0 = ks * 16;
        uint32_t af[2][4];
        #pragma unroll
        for (int mt = 0; mt < 2; mt++) {
            int row = wm * 32 + mt * 16 + (lane & 15);
            int ch  = (k0 >> 3) + (lane >> 4);
            uint32_t addr = asb + row * 128 + ((ch ^ (row & 7)) << 4);
            LDSM_X4(af[mt][0], af[mt][1], af[mt][2], af[mt][3], addr);
        }
        #pragma unroll
        for (int nt = 0; nt < 8; nt++) {
            int krow = k0 + (lane & 15);
            int ncol = wn * 64 + nt * 8;
            uint32_t addr = bsb + krow * 512 + (((ncol >> 3) ^ (krow & 7)) << 4);
            uint32_t b0, b1;
            LDSM_X2T(b0, b1, addr);
            #pragma unroll
            for (int mt = 0; mt < 2; mt++)
                MMA16816(acc[mt][nt][0], acc[mt][nt][1], acc[mt][nt][2], acc[mt][nt][3],
                         af[mt][0], af[mt][1], af[mt][2], af[mt][3], b0, b1);
        }
    }

    bf16* ob = out + (ll)bt * Cc * NN + (ll)(h * Dd) * NN;
    int g4 = lane >> 2, t4 = lane & 3;
    #pragma unroll
    for (int mt = 0; mt < 2; mt++) {
        #pragma unroll
        for (int nt = 0; nt < 8; nt++) {
            int erow = wm * 32 + mt * 16 + g4;
            int col  = n0 + wn * 64 + nt * 8 + t4 * 2;
            float* a = acc[mt][nt];
            __nv_bfloat162 v0 = __floats2bfloat162_rn(a[0], a[1]);
            __nv_bfloat162 v1 = __floats2bfloat162_rn(a[2], a[3]);
            *reinterpret_cast<__nv_bfloat162*>(ob + (ll)erow * NN + col) = v0;
            *reinterpret_cast<__nv_bfloat162*>(ob + (ll)(erow + 8) * NN + col) = v1;
        }
    }
}

// ---------------- fused temporal attention (ST=16, 256 threads, bf16 smem) ----------------
#define ST 16
#define TSMEM (2 * 1024 * 16 * 2 + 256 * 16 * 4)   // 98304 B

__global__ __launch_bounds__(256) void temporal_fused(const bf16* __restrict__ tqkv,
                                                      bf16* __restrict__ out)
{
    extern __shared__ char tsm2[];
    bf16*  ks   = (bf16*)tsm2;
    bf16*  vs   = ks + 1024 * 16;
    float* attw = (float*)(vs + 1024 * 16);

    int b = blockIdx.z, hh = blockIdx.y;
    int s0 = blockIdx.x * ST;
    const ll TN = (ll)Tt * NN;
    const bf16* kb = tqkv + ((ll)b * C3 + Cc + hh * Dd) * TN;
    const bf16* vb = tqkv + ((ll)b * C3 + 2 * Cc + hh * Dd) * TN;
    int tid = threadIdx.x;

    #pragma unroll
    for (int l = 0; l < 16; l++) {
        int idx = l * 256 + tid;
        int arr = idx >> 11;
        int rem = idx & 2047;
        int row = rem >> 1, ch = rem & 1;
        int d = row & 63, j = row >> 6;
        const bf16* src = (arr ? vb : kb) + (ll)d * TN + j * NN + s0 + ch * 8;
        bf16* dst = (arr ? vs : ks) + row * 16 + ch * 8;
        *(uint4*)dst = *(const uint4*)src;
    }
    __syncthreads();

    int sl = tid & 15;
    int i  = tid >> 4;

    {
        const bf16* qb = tqkv + ((ll)b * C3 + hh * Dd) * TN + (ll)i * NN + s0 + sl;
        float acc[16];
        #pragma unroll
        for (int j = 0; j < 16; j++) acc[j] = 0.f;
        for (int d = 0; d < 64; d++) {
            float qv = __bfloat162float(qb[(ll)d * TN]) * 0.125f;
            #pragma unroll
            for (int j = 0; j < 16; j++)
                acc[j] += qv * __bfloat162float(ks[(j * 64 + d) * 16 + sl]);
        }
        float m = acc[0];
        #pragma unroll
        for (int j = 1; j < 16; j++) m = fmaxf(m, acc[j]);
        float sum = 0.f;
        #pragma unroll
        for (int j = 0; j < 16; j++) { acc[j] = __expf(acc[j] - m); sum += acc[j]; }
        float inv = 1.f / sum;
        #pragma unroll
        for (int j = 0; j < 16; j++)
            attw[(i * 16 + j) * 16 + sl] = acc[j] * inv;
    }
    __syncthreads();

    int dg = i;
    bf16* ob = out + ((ll)b * Cc + hh * Dd + dg * 4) * TN + s0 + sl;
    for (int ii = 0; ii < 16; ii++) {
        float a0 = 0.f, a1 = 0.f, a2 = 0.f, a3 = 0.f;
        #pragma unroll
        for (int j = 0; j < 16; j++) {
            float av = attw[(ii * 16 + j) * 16 + sl];
            a0 += av * __bfloat162float(vs[(j * 64 + dg * 4 + 0) * 16 + sl]);
            a1 += av * __bfloat162float(vs[(j * 64 + dg * 4 + 1) * 16 + sl]);
            a2 += av * __bfloat162float(vs[(j * 64 + dg * 4 + 2) * 16 + sl]);
            a3 += av * __bfloat162float(vs[(j * 64 + dg * 4 + 3) * 16 + sl]);
        }
        ll t_off = (ll)ii * NN;
        ob[t_off + 0 * TN] = __float2bfloat16(a0);
        ob[t_off + 1 * TN] = __float2bfloat16(a1);
        ob[t_off + 2 * TN] = __float2bfloat16(a2);
        ob[t_off + 3 * TN] = __float2bfloat16(a3);
    }
}

// ---------------- launch ----------------
extern "C" void kernel_launch(void* const* d_in, const int* in_sizes, int n_in,
                              void* d_out, int out_size)
{
    const float* x      = (const float*)d_in[0];
    const float* w_sqkv = (const float*)d_in[1];
    const float* w_sout = (const float*)d_in[2];
    const float* b_sout = (const float*)d_in[3];
    const float* w_tqkv = (const float*)d_in[4];
    const float* w_tout = (const float*)d_in[5];
    float* out = (float*)d_out;

    bf16 *wsqkv_t, *wsout_c, *wtqkv_t, *wtout_t, *wcomb, *xbf, *sqkv, *ctx_ed, *sattn_bf, *tqkv, *tout_bf;
    float *bcomb;
    cudaGetSymbolAddress((void**)&wsqkv_t, g_wsqkv_t);
    cudaGetSymbolAddress((void**)&wsout_c, g_wsout_c);
    cudaGetSymbolAddress((void**)&wtqkv_t, g_wtqkv_t);
    cudaGetSymbolAddress((void**)&wtout_t, g_wtout_t);
    cudaGetSymbolAddress((void**)&wcomb,   g_wcomb);
    cudaGetSymbolAddress((void**)&bcomb,   g_bcomb);
    cudaGetSymbolAddress((void**)&xbf,     g_xbf);
    cudaGetSymbolAddress((void**)&sqkv,    g_sqkv);
    cudaGetSymbolAddress((void**)&ctx_ed,  g_ctx_ed);
    cudaGetSymbolAddress((void**)&sattn_bf,g_sattn_bf);
    cudaGetSymbolAddress((void**)&tqkv,    g_tqkv);
    cudaGetSymbolAddress((void**)&tout_bf, g_tout_bf);

    static int attr_set = 0;
    static cudaStream_t s2;
    static cudaEvent_t evF, evJ, evK, evS;
    if (!attr_set) {
        cudaFuncSetAttribute(temporal_fused, cudaFuncAttributeMaxDynamicSharedMemorySize, TSMEM);
        cudaStreamCreateWithFlags(&s2, cudaStreamNonBlocking);
        cudaEventCreateWithFlags(&evF, cudaEventDisableTiming);
        cudaEventCreateWithFlags(&evJ, cudaEventDisableTiming);
        cudaEventCreateWithFlags(&evK, cudaEventDisableTiming);
        cudaEventCreateWithFlags(&evS, cudaEventDisableTiming);
        attr_set = 1;
    }

    const ll TN = (ll)Tt * NN;
    const ll XB = (ll)Cc * TN;
    const ll QKV_CO = (ll)Tt * C3 * NN;   // cOuter for sqkv
    const ll QKV_CI = (ll)C3 * NN;        // cInner for sqkv

    // 0) merged prep
    prep_all<<<PREP_BLOCKS, 256>>>(x, w_sqkv, w_sout, w_tqkv, w_tout, b_sout,
                                   xbf, wsqkv_t, wsout_c, wtqkv_t, wtout_t, bcomb);

    // fork: combine GEMM on s2
    cudaEventRecord(evF, 0);
    cudaStreamWaitEvent(s2, evF, 0);
    gemm_bf16<<<dim3(C3 / 128, Cc / 128, 1), 256, 0, s2>>>(
        wsout_c, wtqkv_t, nullptr, wcomb, nullptr, nullptr,
        Cc, Cc, 1, 0,
        0, 0, C3,
        0, 0, C3);
    cudaEventRecord(evJ, s2);

    // 1a) q projection (o 0..511), fused q-softmax
    gemm_bf16<<<dim3(NN / 128, Cc / 128, BT), 256>>>(
        wsqkv_t, xbf, nullptr, sqkv, nullptr, nullptr,
        Cc, C3, Tt, 1,
        XB, NN, TN,
        QKV_CO, QKV_CI, NN);

    // 1b) k projection (o 512..1023)
    gemm_bf16<<<dim3(NN / 128, Cc / 128, BT), 256>>>(
        wsqkv_t + Cc, xbf, nullptr, sqkv + (ll)Cc * NN, nullptr, nullptr,
        Cc, C3, Tt, 0,
        XB, NN, TN,
        QKV_CO, QKV_CI, NN);
    cudaEventRecord(evK, 0);

    // 1c) v projection (o 1024..1535) — concurrent with softmax_k on s2
    gemm_bf16<<<dim3(NN / 128, Cc / 128, BT), 256>>>(
        wsqkv_t + 2 * Cc, xbf, nullptr, sqkv + (ll)(2 * Cc) * NN, nullptr, nullptr,
        Cc, C3, Tt, 0,
        XB, NN, TN,
        QKV_CO, QKV_CI, NN);

    // 2) k softmax on s2, overlapped with v projection
    cudaStreamWaitEvent(s2, evK, 0);
    softmax_k<<<dim3(Cc, BT), 256, 0, s2>>>(sqkv);
    cudaEventRecord(evS, s2);

    // 3) ctx -> ctx_ed (needs k-softmax + v)
    cudaStreamWaitEvent(0, evS, 0);
    ctx_mma<<<dim3(HEADS, BT), 128>>>(sqkv, ctx_ed);

    // 4) apply -> sattn bf16 [bt][c][n]
    attn_apply_mma<<<dim3(NN / 256, HEADS, BT), 256>>>(ctx_ed, sqkv, sattn_bf);

    // join: wcomb/bcomb ready before GEMM5
    cudaStreamWaitEvent(0, evJ, 0);

    // 5) fused temporal qkv
    gemm_bf16<<<dim3(NN / 128, C3 / 128, BT), 256>>>(
        wcomb, sattn_bf, nullptr, tqkv, bcomb, nullptr,
        Cc, C3, Tt, 0,
        (ll)Tt * Cc * NN, (ll)Cc * NN, NN,
        (ll)C3 * TN, NN, TN);

    // 6) fused temporal attention
    temporal_fused<<<dim3(NN / ST, HEADS, Bb), 256, TSMEM>>>(tqkv, tout_bf);

    // 7) temporal proj + residual -> out fp32
    gemm_bf16<<<dim3((int)(TN / 128), Cc / 128, Bb), 256>>>(
        wtout_t, tout_bf, out, nullptr, nullptr, x,
        Cc, Cc, 1, 0,
        XB, 0, TN,
        XB, 0, TN);
}

// round 16
// speedup vs baseline: 1.0135x; 1.0135x over previous
#include <cuda_runtime.h>
#include <cuda_bf16.h>
#include <math.h>
#include <stdint.h>

#define Bb 2
#define Cc 512
#define Tt 16
#define NN 1024
#define HEADS 8
#define Dd 64
#define BT 32
#define C3 1536

typedef __nv_bfloat16 bf16;
typedef long long ll;

// ---------------- scratch (device globals) ----------------
__device__ __align__(16) bf16  g_wsqkv_t[Cc * C3];   // Wt[k][o]
__device__ __align__(16) bf16  g_wsout_c[Cc * Cc];   // W_sout[o][c] direct
__device__ __align__(16) bf16  g_wtqkv_t[Cc * C3];   // W_tqkv^T [o][p]
__device__ __align__(16) bf16  g_wtout_t[Cc * Cc];
__device__ __align__(16) bf16  g_wcomb[Cc * C3];     // (W_tqkv W_sout)^T [c][p]
__device__ __align__(16) float g_bcomb[C3];          // W_tqkv b_sout
__device__ __align__(16) bf16  g_xbf[Bb * Cc * Tt * NN];
__device__ __align__(16) bf16  g_sqkv[BT * C3 * NN];
__device__ __align__(16) bf16  g_ctx_ed[BT * HEADS * Dd * Dd];
__device__ __align__(16) bf16  g_sattn_bf[BT * Cc * NN];       // [bt][c][n]
__device__ __align__(16) bf16  g_tqkv[Bb * C3 * Tt * NN];
__device__ __align__(16) bf16  g_tout_bf[Bb * Cc * Tt * NN];

// ---------------- helpers ----------------
__device__ __forceinline__ uint32_t smem_u32(const void* p) {
    uint32_t a;
    asm("{ .reg .u64 t; cvta.to.shared.u64 t, %1; cvt.u32.u64 %0, t; }" : "=r"(a) : "l"(p));
    return a;
}
#define CP_ASYNC(dst, src) asm volatile("cp.async.cg.shared.global [%0],[%1],16;\n" :: "r"(dst), "l"(src) : "memory")
#define CP_COMMIT()        asm volatile("cp.async.commit_group;\n" ::: "memory")
#define CP_WAIT0()         asm volatile("cp.async.wait_group 0;\n" ::: "memory")
#define CP_WAIT1()         asm volatile("cp.async.wait_group 1;\n" ::: "memory")

#define LDSM_X4(r0,r1,r2,r3,addr) \
    asm volatile("ldmatrix.sync.aligned.m8n8.x4.shared.b16 {%0,%1,%2,%3},[%4];" \
                 : "=r"(r0),"=r"(r1),"=r"(r2),"=r"(r3) : "r"(addr))
#define LDSM_X4T(r0,r1,r2,r3,addr) \
    asm volatile("ldmatrix.sync.aligned.m8n8.x4.trans.shared.b16 {%0,%1,%2,%3},[%4];" \
                 : "=r"(r0),"=r"(r1),"=r"(r2),"=r"(r3) : "r"(addr))
#define LDSM_X2T(r0,r1,addr) \
    asm volatile("ldmatrix.sync.aligned.m8n8.x2.trans.shared.b16 {%0,%1},[%2];" \
                 : "=r"(r0),"=r"(r1) : "r"(addr))
#define MMA16816(d0,d1,d2,d3,a0,a1,a2,a3,b0,b1) \
    asm volatile("mma.sync.aligned.m16n8k16.row.col.f32.bf16.bf16.f32 " \
                 "{%0,%1,%2,%3},{%4,%5,%6,%7},{%8,%9},{%0,%1,%2,%3};" \
                 : "+f"(d0),"+f"(d1),"+f"(d2),"+f"(d3) \
                 : "r"(a0),"r"(a1),"r"(a2),"r"(a3),"r"(b0),"r"(b1))

// ---------------- merged prep: f2b(x) + weight conversions + bcomb ----------------
#define F2B_BLOCKS  16384
#define CONV_BLOCKS 8192
#define PREP_BLOCKS (F2B_BLOCKS + CONV_BLOCKS + 192)

__global__ __launch_bounds__(256) void prep_all(
    const float* __restrict__ x,
    const float* __restrict__ w1, const float* __restrict__ w2,
    const float* __restrict__ w3, const float* __restrict__ w4,
    const float* __restrict__ b_sout,
    bf16* __restrict__ xbf,
    bf16* __restrict__ o1, bf16* __restrict__ o2,
    bf16* __restrict__ o3, bf16* __restrict__ o4,
    float* __restrict__ bcomb)
{
    int blk = blockIdx.x;
    int tid = threadIdx.x;
    if (blk < F2B_BLOCKS) {
        int i = (blk * 256 + tid) * 4;
        float4 v = *(const float4*)(x + i);
        __nv_bfloat162 p0 = __floats2bfloat162_rn(v.x, v.y);
        __nv_bfloat162 p1 = __floats2bfloat162_rn(v.z, v.w);
        uint2 u;
        u.x = *(uint32_t*)&p0;
        u.y = *(uint32_t*)&p1;
        *(uint2*)(xbf + i) = u;
    } else if (blk < F2B_BLOCKS + CONV_BLOCKS) {
        const int N1 = C3 * Cc, N2 = Cc * Cc;
        int idx = (blk - F2B_BLOCKS) * 256 + tid;
        if (idx < N1) {
            int o = idx % C3, k = idx / C3;
            o1[idx] = __float2bfloat16(w1[(ll)o * Cc + k]);
        } else if (idx < N1 + N2) {
            int rem = idx - N1;
            o2[rem] = __float2bfloat16(w2[rem]);
        } else if (idx < 2 * N1 + N2) {
            int rem = idx - N1 - N2;
            int o = rem % C3, k = rem / C3;
            o3[rem] = __float2bfloat16(w3[(ll)o * Cc + k]);
        } else {
            int rem = idx - 2 * N1 - N2;
            int o = rem % Cc, k = rem / Cc;
            o4[rem] = __float2bfloat16(w4[(ll)o * Cc + k]);
        }
    } else {
        int p = (blk - F2B_BLOCKS - CONV_BLOCKS) * 8 + (tid >> 5);
        int lane = tid & 31;
        if (p >= C3) return;
        const float* wr = w3 + (ll)p * Cc;
        float s = 0.f;
        for (int o = lane; o < Cc; o += 32) s += wr[o] * b_sout[o];
        #pragma unroll
        for (int off = 16; off; off >>= 1) s += __shfl_xor_sync(0xffffffffu, s, off);
        if (lane == 0) bcomb[p] = s;
    }
}

// ---------------- bf16 tensor-core GEMM (128x128x32, 3-stage, optional fused q-softmax) ----------------
__global__ __launch_bounds__(256, 2) void gemm_bf16(
    const bf16* __restrict__ Wt,   // [K][ldA]
    const bf16* __restrict__ X,
    float* __restrict__ Cf,
    bf16* __restrict__ Cb,
    const float* __restrict__ bias,
    const float* __restrict__ res,
    int K, int ldA, int gDiv, int qsmax,
    ll xOuter, ll xInner, ll xRow,
    ll cOuter, ll cInner, ll cRow)
{
    __shared__ bf16 As[3][32][128];
    __shared__ bf16 Bs[3][32][128];

    int g = blockIdx.z;
    ll gq = g / gDiv, gr = g % gDiv;
    const bf16* Xb = X + gq * xOuter + gr * xInner;
    ll cbase = gq * cOuter + gr * cInner;

    int n0 = blockIdx.x * 128;
    int o0 = blockIdx.y * 128;

    int tid = threadIdx.x;
    int lane = tid & 31, warp = tid >> 5;
    int wm = warp >> 2, wn = warp & 3;

    uint32_t asb = smem_u32(&As[0][0][0]);
    uint32_t bsb = smem_u32(&Bs[0][0][0]);

    float acc[4][4][4];
    #pragma unroll
    for (int a = 0; a < 4; a++)
        #pragma unroll
        for (int b = 0; b < 4; b++)
            #pragma unroll
            for (int c = 0; c < 4; c++) acc[a][b][c] = 0.f;

    int nkt = K / 32;

    #define ISSUE_TILE(kt, buf) do {                                                     \
        int k0_ = (kt) * 32;                                                             \
        _Pragma("unroll")                                                                \
        for (int i_ = 0; i_ < 2; i_++) {                                                 \
            int idx_ = tid + 256 * i_;                                                   \
            int row_ = idx_ >> 4, ch_ = idx_ & 15;                                       \
            const bf16* sA = Wt + (ll)(k0_ + row_) * ldA + o0 + ch_ * 8;                 \
            uint32_t dA = asb + (buf) * 8192 + row_ * 256 + (((ch_) ^ (row_ & 7)) << 4); \
            CP_ASYNC(dA, sA);                                                            \
            const bf16* sB = Xb + (ll)(k0_ + row_) * xRow + n0 + ch_ * 8;                \
            uint32_t dB = bsb + (buf) * 8192 + row_ * 256 + (((ch_) ^ (row_ & 7)) << 4); \
            CP_ASYNC(dB, sB);                                                            \
        }                                                                                \
    } while (0)

    ISSUE_TILE(0, 0);
    CP_COMMIT();
    ISSUE_TILE(1, 1);
    CP_COMMIT();

    int r7 = lane & 7, sub = lane >> 3;
    int brow_lo = lane & 15;

    for (int kt = 0; kt < nkt; kt++) {
        CP_WAIT1();
        __syncthreads();
        if (kt + 2 < nkt) {
            int nb = (kt + 2) % 3;
            ISSUE_TILE(kt + 2, nb);
        }
        CP_COMMIT();
        int buf = kt % 3;
        uint32_t abase = asb + buf * 8192;
        uint32_t bbase = bsb + buf * 8192;

        #pragma unroll
        for (int ks = 0; ks < 2; ks++) {
            uint32_t af[4][4];
            uint32_t bf_[4][2];
            #pragma unroll
            for (int mt = 0; mt < 4; mt++) {
                int krow = ks * 16 + r7 + ((sub >> 1) << 3);
                int mcol = wm * 64 + mt * 16 + ((sub & 1) << 3);
                uint32_t addr = abase + krow * 256 + ((((mcol >> 3)) ^ (krow & 7)) << 4);
                LDSM_X4T(af[mt][0], af[mt][1], af[mt][2], af[mt][3], addr);
            }
            #pragma unroll
            for (int nt = 0; nt < 4; nt++) {
                int brow = ks * 16 + brow_lo;
                int ncol = wn * 32 + nt * 8;
                uint32_t addr = bbase + brow * 256 + ((((ncol >> 3)) ^ (brow & 7)) << 4);
                LDSM_X2T(bf_[nt][0], bf_[nt][1], addr);
            }
            #pragma unroll
            for (int mt = 0; mt < 4; mt++)
                #pragma unroll
                for (int nt = 0; nt < 4; nt++)
                    MMA16816(acc[mt][nt][0], acc[mt][nt][1], acc[mt][nt][2], acc[mt][nt][3],
                             af[mt][0], af[mt][1], af[mt][2], af[mt][3],
                             bf_[nt][0], bf_[nt][1]);
        }
    }

    if (qsmax && o0 < Cc) {
        #pragma unroll
        for (int nt = 0; nt < 4; nt++) {
            #pragma unroll
            for (int c = 0; c < 2; c++) {
                float m = -INFINITY;
                #pragma unroll
                for (int mt = 0; mt < 4; mt++) {
                    m = fmaxf(m, acc[mt][nt][c]);
                    m = fmaxf(m, acc[mt][nt][c + 2]);
                }
                m = fmaxf(m, __shfl_xor_sync(0xffffffffu, m, 4));
                m = fmaxf(m, __shfl_xor_sync(0xffffffffu, m, 8));
                m = fmaxf(m, __shfl_xor_sync(0xffffffffu, m, 16));
                float s = 0.f;
                #pragma unroll
                for (int mt = 0; mt < 4; mt++) {
                    acc[mt][nt][c]     = __expf(acc[mt][nt][c] - m);
                    acc[mt][nt][c + 2] = __expf(acc[mt][nt][c + 2] - m);
                    s += acc[mt][nt][c] + acc[mt][nt][c + 2];
                }
                s += __shfl_xor_sync(0xffffffffu, s, 4);
                s += __shfl_xor_sync(0xffffffffu, s, 8);
                s += __shfl_xor_sync(0xffffffffu, s, 16);
                float inv = 0.125f / s;
                #pragma unroll
                for (int mt = 0; mt < 4; mt++) {
                    acc[mt][nt][c]     *= inv;
                    acc[mt][nt][c + 2] *= inv;
                }
            }
        }
    }

    int g4 = lane >> 2, t4 = lane & 3;
    #pragma unroll
    for (int mt = 0; mt < 4; mt++) {
        #pragma unroll
        for (int nt = 0; nt < 4; nt++) {
            int orow = o0 + wm * 64 + mt * 16 + g4;
            int col  = n0 + wn * 32 + nt * 8 + t4 * 2;
            ll off0 = cbase + (ll)orow * cRow + col;
            ll off1 = off0 + 8 * cRow;
            float b0 = bias ? bias[orow] : 0.f;
            float b1 = bias ? bias[orow + 8] : 0.f;
            float* a = acc[mt][nt];
            if (Cb) {
                __nv_bfloat162 v0 = __floats2bfloat162_rn(a[0] + b0, a[1] + b0);
                __nv_bfloat162 v1 = __floats2bfloat162_rn(a[2] + b1, a[3] + b1);
                *reinterpret_cast<__nv_bfloat162*>(Cb + off0) = v0;
                *reinterpret_cast<__nv_bfloat162*>(Cb + off1) = v1;
            } else {
                float2 r0 = make_float2(0.f, 0.f), r1 = make_float2(0.f, 0.f);
                if (res) { r0 = *(const float2*)(res + off0); r1 = *(const float2*)(res + off1); }
                float2 o0v = make_float2(a[0] + b0 + r0.x, a[1] + b0 + r0.y);
                float2 o1v = make_float2(a[2] + b1 + r1.x, a[3] + b1 + r1.y);
                *(float2*)(Cf + off0) = o0v;
                *(float2*)(Cf + off1) = o1v;
            }
        }
    }
    #undef ISSUE_TILE
}

// ---------------- k softmax (over n, bf16 in/out, vectorized) ----------------
__global__ __launch_bounds__(256) void softmax_k(bf16* __restrict__ p)
{
    bf16* row = p + (ll)blockIdx.y * C3 * NN + (ll)(Cc + blockIdx.x) * NN;
    int tid = threadIdx.x;
    uint2 u = *(uint2*)(row + tid * 4);
    __nv_bfloat162 p0 = *(__nv_bfloat162*)&u.x;
    __nv_bfloat162 p1 = *(__nv_bfloat162*)&u.y;
    float v[4];
    v[0] = __bfloat162float(p0.x); v[1] = __bfloat162float(p0.y);
    v[2] = __bfloat162float(p1.x); v[3] = __bfloat162float(p1.y);
    float m = fmaxf(fmaxf(v[0], v[1]), fmaxf(v[2], v[3]));
    __shared__ float red[8];
    #pragma unroll
    for (int o = 16; o; o >>= 1) m = fmaxf(m, __shfl_xor_sync(0xffffffffu, m, o));
    if ((tid & 31) == 0) red[tid >> 5] = m;
    __syncthreads();
    m = red[0];
    #pragma unroll
    for (int wv = 1; wv < 8; wv++) m = fmaxf(m, red[wv]);
    __syncthreads();
    float s = 0.f;
    #pragma unroll
    for (int k = 0; k < 4; k++) { v[k] = __expf(v[k] - m); s += v[k]; }
    #pragma unroll
    for (int o = 16; o; o >>= 1) s += __shfl_xor_sync(0xffffffffu, s, o);
    if ((tid & 31) == 0) red[tid >> 5] = s;
    __syncthreads();
    s = 0.f;
    #pragma unroll
    for (int wv = 0; wv < 8; wv++) s += red[wv];
    float inv = 1.f / s;
    __nv_bfloat162 q0 = __floats2bfloat162_rn(v[0] * inv, v[1] * inv);
    __nv_bfloat162 q1 = __floats2bfloat162_rn(v[2] * inv, v[3] * inv);
    uint2 w;
    w.x = *(uint32_t*)&q0;
    w.y = *(uint32_t*)&q1;
    *(uint2*)(row + tid * 4) = w;
}

// ---------------- ctx (mma.sync): ctx_ed[e][d] = sum_n k[d][n] v[e][n] ----------------
__global__ __launch_bounds__(128) void ctx_mma(const bf16* __restrict__ qkv,
                                               bf16* __restrict__ ctx_ed)
{
    int h = blockIdx.x, bt = blockIdx.y;
    const bf16* kbase = qkv + (ll)bt * C3 * NN + (ll)(Cc + h * Dd) * NN;
    const bf16* vbase = qkv + (ll)bt * C3 * NN + (ll)(2 * Cc + h * Dd) * NN;

    __shared__ bf16 Ks[2][64 * 64];
    __shared__ bf16 Vs[2][64 * 64];
    uint32_t ksb = smem_u32(&Ks[0][0]);
    uint32_t vsb = smem_u32(&Vs[0][0]);

    int tid = threadIdx.x;
    int lane = tid & 31, warp = tid >> 5;
    int m0 = warp * 16;

    float acc[8][4] = {};

    #define CTX_ISSUE(c, buf) do {                                                  \
        _Pragma("unroll")                                                           \
        for (int i_ = 0; i_ < 8; i_++) {                                            \
            int idx_ = i_ * 128 + tid;                                              \
            int mat_ = idx_ >> 9;                                                   \
            int rem_ = idx_ & 511;                                                  \
            int row_ = rem_ >> 3, ch_ = rem_ & 7;                                   \
            const bf16* src_ = (mat_ ? vbase : kbase) + (ll)row_ * NN + (c) * 64 + ch_ * 8; \
            uint32_t dst_ = (mat_ ? vsb : ksb) + (buf) * 8192 + row_ * 128 + ((ch_ ^ (row_ & 7)) << 4); \
            CP_ASYNC(dst_, src_);                                                   \
        }                                                                           \
    } while (0)

    CTX_ISSUE(0, 0);
    CP_COMMIT();

    for (int c = 0; c < 16; c++) {
        CP_WAIT0();
        __syncthreads();
        if (c + 1 < 16) { CTX_ISSUE(c + 1, (c + 1) & 1); CP_COMMIT(); }
        int buf = c & 1;
        uint32_t ka = ksb + buf * 8192;
        uint32_t va = vsb + buf * 8192;
        #pragma unroll
        for (int ks = 0; ks < 4; ks++) {
            int k0 = ks * 16;
            uint32_t a0, a1, a2, a3;
            {
                int row = m0 + (lane & 15);
                int ch  = (k0 >> 3) + (lane >> 4);
                uint32_t addr = ka + row * 128 + ((ch ^ (row & 7)) << 4);
                LDSM_X4(a0, a1, a2, a3, addr);
            }
            #pragma unroll
            for (int nb = 0; nb < 4; nb++) {
                int row = nb * 16 + ((lane >> 4) << 3) + (lane & 7);
                int ch  = (k0 >> 3) + ((lane >> 3) & 1);
                uint32_t addr = va + row * 128 + ((ch ^ (row & 7)) << 4);
                uint32_t r0, r1, r2, r3;
                LDSM_X4(r0, r1, r2, r3, addr);
                MMA16816(acc[nb*2][0],   acc[nb*2][1],   acc[nb*2][2],   acc[nb*2][3],
                         a0, a1, a2, a3, r0, r1);
                MMA16816(acc[nb*2+1][0], acc[nb*2+1][1], acc[nb*2+1][2], acc[nb*2+1][3],
                         a0, a1, a2, a3, r2, r3);
            }
        }
    }
    #undef CTX_ISSUE

    bf16* cb = ctx_ed + ((ll)bt * HEADS + h) * (Dd * Dd);
    int g4 = lane >> 2, t4 = lane & 3;
    #pragma unroll
    for (int nt = 0; nt < 8; nt++) {
        int e0 = nt * 8 + t4 * 2;
        int d0 = m0 + g4;
        cb[(e0)     * Dd + d0]     = __float2bfloat16(acc[nt][0]);
        cb[(e0 + 1) * Dd + d0]     = __float2bfloat16(acc[nt][1]);
        cb[(e0)     * Dd + d0 + 8] = __float2bfloat16(acc[nt][2]);
        cb[(e0 + 1) * Dd + d0 + 8] = __float2bfloat16(acc[nt][3]);
    }
}

// ---------------- attn apply: out[e][n] -> sattn [bt][c][n] ----------------
__global__ __launch_bounds__(256) void attn_apply_mma(const bf16* __restrict__ ctx_ed,
                                                      const bf16* __restrict__ qkv,
                                                      bf16* __restrict__ out)
{
    int n0 = blockIdx.x * 256, h = blockIdx.y, bt = blockIdx.z;
    const bf16* cbase = ctx_ed + ((ll)bt * HEADS + h) * (Dd * Dd);
    const bf16* qbase = qkv + (ll)bt * C3 * NN + (ll)(h * Dd) * NN;

    __shared__ bf16 Asm[64 * 64];
    __shared__ bf16 Bsm[64 * 256];
    uint32_t asb = smem_u32(&Asm[0]);
    uint32_t bsb = smem_u32(&Bsm[0]);

    int tid = threadIdx.x;
    int lane = tid & 31, warp = tid >> 5;
    int wm = warp >> 2, wn = warp & 3;

    #pragma unroll
    for (int i = 0; i < 2; i++) {
        int idx = i * 256 + tid;
        int row = idx >> 3, ch = idx & 7;
        const bf16* src = cbase + row * Dd + ch * 8;
        uint32_t dst = asb + row * 128 + ((ch ^ (row & 7)) << 4);
        CP_ASYNC(dst, src);
    }
    #pragma unroll
    for (int i = 0; i < 8; i++) {
        int idx = i * 256 + tid;
        int row = idx >> 5, ch = idx & 31;
        const bf16* src = qbase + (ll)row * NN + n0 + ch * 8;
        uint32_t dst = bsb + row * 512 + ((ch ^ (row & 7)) << 4);
        CP_ASYNC(dst, src);
    }
    CP_COMMIT();
    CP_WAIT0();
    __syncthreads();

    float acc[2][8][4] = {};
    #pragma unroll
    for (int ks = 0; ks < 4; ks++) {
        int k0 = ks * 16;
        uint32_t af[2][4];
        #pragma unroll
        for (int mt = 0; mt < 2; mt++) {
            int row = wm * 32 + mt * 16 + (lane & 15);
            int ch  = (k0 >> 3) + (lane >> 4);
            uint32_t addr = asb + row * 128 + ((ch ^ (row & 7)) << 4);
            LDSM_X4(af[mt][0], af[mt][1], af[mt][2], af[mt][3], addr);
        }
        #pragma unroll
        for (int nt = 0; nt < 8; nt++) {
            int krow = k0 + (lane & 15);
            int ncol = wn * 64 + nt * 8;
            uint32_t addr = bsb + krow * 512 + (((ncol >> 3) ^ (krow & 7)) << 4);
            uint32_t b0, b1;
            LDSM_X2T(b0, b1, addr);
            #pragma unroll
            for (int mt = 0; mt < 2; mt++)
                MMA16816(acc[mt][nt][0], acc[mt][nt][1], acc[mt][nt][2], acc[mt][nt][3],
                         af[mt][0], af[mt][1], af[mt][2], af[mt][3], b0, b1);
        }
    }

    bf16* ob = out + (ll)bt * Cc * NN + (ll)(h * Dd) * NN;
    int g4 = lane >> 2, t4 = lane & 3;
    #pragma unroll
    for (int mt = 0; mt < 2; mt++) {
        #pragma unroll
        for (int nt = 0; nt < 8; nt++) {
            int erow = wm * 32 + mt * 16 + g4;
            int col  = n0 + wn * 64 + nt * 8 + t4 * 2;
            float* a = acc[mt][nt];
            __nv_bfloat162 v0 = __floats2bfloat162_rn(a[0], a[1]);
            __nv_bfloat162 v1 = __floats2bfloat162_rn(a[2], a[3]);
            *reinterpret_cast<__nv_bfloat162*>(ob + (ll)erow * NN + col) = v0;
            *reinterpret_cast<__nv_bfloat162*>(ob + (ll)(erow + 8) * NN + col) = v1;
        }
    }
}

// ---------------- fused temporal attention (ST=16, 256 threads, bf16 smem) ----------------
#define ST 16
#define TSMEM (2 * 1024 * 16 * 2 + 256 * 16 * 4)   // 98304 B

__global__ __launch_bounds__(256) void temporal_fused(const bf16* __restrict__ tqkv,
                                                      bf16* __restrict__ out)
{
    extern __shared__ char tsm2[];
    bf16*  ks   = (bf16*)tsm2;
    bf16*  vs   = ks + 1024 * 16;
    float* attw = (float*)(vs + 1024 * 16);

    int b = blockIdx.z, hh = blockIdx.y;
    int s0 = blockIdx.x * ST;
    const ll TN = (ll)Tt * NN;
    const bf16* kb = tqkv + ((ll)b * C3 + Cc + hh * Dd) * TN;
    const bf16* vb = tqkv + ((ll)b * C3 + 2 * Cc + hh * Dd) * TN;
    int tid = threadIdx.x;

    #pragma unroll
    for (int l = 0; l < 16; l++) {
        int idx = l * 256 + tid;
        int arr = idx >> 11;
        int rem = idx & 2047;
        int row = rem >> 1, ch = rem & 1;
        int d = row & 63, j = row >> 6;
        const bf16* src = (arr ? vb : kb) + (ll)d * TN + j * NN + s0 + ch * 8;
        bf16* dst = (arr ? vs : ks) + row * 16 + ch * 8;
        *(uint4*)dst = *(const uint4*)src;
    }
    __syncthreads();

    int sl = tid & 15;
    int i  = tid >> 4;

    {
        const bf16* qb = tqkv + ((ll)b * C3 + hh * Dd) * TN + (ll)i * NN + s0 + sl;
        float acc[16];
        #pragma unroll
        for (int j = 0; j < 16; j++) acc[j] = 0.f;
        for (int d = 0; d < 64; d++) {
            float qv = __bfloat162float(qb[(ll)d * TN]) * 0.125f;
            #pragma unroll
            for (int j = 0; j < 16; j++)
                acc[j] += qv * __bfloat162float(ks[(j * 64 + d) * 16 + sl]);
        }
        float m = acc[0];
        #pragma unroll
        for (int j = 1; j < 16; j++) m = fmaxf(m, acc[j]);
        float sum = 0.f;
        #pragma unroll
        for (int j = 0; j < 16; j++) { acc[j] = __expf(acc[j] - m); sum += acc[j]; }
        float inv = 1.f / sum;
        #pragma unroll
        for (int j = 0; j < 16; j++)
            attw[(i * 16 + j) * 16 + sl] = acc[j] * inv;
    }
    __syncthreads();

    int dg = i;
    bf16* ob = out + ((ll)b * Cc + hh * Dd + dg * 4) * TN + s0 + sl;
    for (int ii = 0; ii < 16; ii++) {
        float a0 = 0.f, a1 = 0.f, a2 = 0.f, a3 = 0.f;
        #pragma unroll
        for (int j = 0; j < 16; j++) {
            float av = attw[(ii * 16 + j) * 16 + sl];
            a0 += av * __bfloat162float(vs[(j * 64 + dg * 4 + 0) * 16 + sl]);
            a1 += av * __bfloat162float(vs[(j * 64 + dg * 4 + 1) * 16 + sl]);
            a2 += av * __bfloat162float(vs[(j * 64 + dg * 4 + 2) * 16 + sl]);
            a3 += av * __bfloat162float(vs[(j * 64 + dg * 4 + 3) * 16 + sl]);
        }
        ll t_off = (ll)ii * NN;
        ob[t_off + 0 * TN] = __float2bfloat16(a0);
        ob[t_off + 1 * TN] = __float2bfloat16(a1);
        ob[t_off + 2 * TN] = __float2bfloat16(a2);
        ob[t_off + 3 * TN] = __float2bfloat16(a3);
    }
}

// ---------------- launch ----------------
extern "C" void kernel_launch(void* const* d_in, const int* in_sizes, int n_in,
                              void* d_out, int out_size)
{
    const float* x      = (const float*)d_in[0];
    const float* w_sqkv = (const float*)d_in[1];
    const float* w_sout = (const float*)d_in[2];
    const float* b_sout = (const float*)d_in[3];
    const float* w_tqkv = (const float*)d_in[4];
    const float* w_tout = (const float*)d_in[5];
    float* out = (float*)d_out;

    bf16 *wsqkv_t, *wsout_c, *wtqkv_t, *wtout_t, *wcomb, *xbf, *sqkv, *ctx_ed, *sattn_bf, *tqkv, *tout_bf;
    float *bcomb;
    cudaGetSymbolAddress((void**)&wsqkv_t, g_wsqkv_t);
    cudaGetSymbolAddress((void**)&wsout_c, g_wsout_c);
    cudaGetSymbolAddress((void**)&wtqkv_t, g_wtqkv_t);
    cudaGetSymbolAddress((void**)&wtout_t, g_wtout_t);
    cudaGetSymbolAddress((void**)&wcomb,   g_wcomb);
    cudaGetSymbolAddress((void**)&bcomb,   g_bcomb);
    cudaGetSymbolAddress((void**)&xbf,     g_xbf);
    cudaGetSymbolAddress((void**)&sqkv,    g_sqkv);
    cudaGetSymbolAddress((void**)&ctx_ed,  g_ctx_ed);
    cudaGetSymbolAddress((void**)&sattn_bf,g_sattn_bf);
    cudaGetSymbolAddress((void**)&tqkv,    g_tqkv);
    cudaGetSymbolAddress((void**)&tout_bf, g_tout_bf);

    static int attr_set = 0;
    static cudaStream_t s2;
    static cudaEvent_t evF, evJ, evK, evS;
    if (!attr_set) {
        cudaFuncSetAttribute(temporal_fused, cudaFuncAttributeMaxDynamicSharedMemorySize, TSMEM);
        cudaStreamCreateWithFlags(&s2, cudaStreamNonBlocking);
        cudaEventCreateWithFlags(&evF, cudaEventDisableTiming);
        cudaEventCreateWithFlags(&evJ, cudaEventDisableTiming);
        cudaEventCreateWithFlags(&evK, cudaEventDisableTiming);
        cudaEventCreateWithFlags(&evS, cudaEventDisableTiming);
        attr_set = 1;
    }

    const ll TN = (ll)Tt * NN;
    const ll XB = (ll)Cc * TN;
    const ll QKV_CO = (ll)Tt * C3 * NN;
    const ll QKV_CI = (ll)C3 * NN;

    // 0) merged prep
    prep_all<<<PREP_BLOCKS, 256>>>(x, w_sqkv, w_sout, w_tqkv, w_tout, b_sout,
                                   xbf, wsqkv_t, wsout_c, wtqkv_t, wtout_t, bcomb);

    // fork: combine GEMM on s2
    cudaEventRecord(evF, 0);
    cudaStreamWaitEvent(s2, evF, 0);
    gemm_bf16<<<dim3(C3 / 128, Cc / 128, 1), 256, 0, s2>>>(
        wsout_c, wtqkv_t, nullptr, wcomb, nullptr, nullptr,
        Cc, Cc, 1, 0,
        0, 0, C3,
        0, 0, C3);
    cudaEventRecord(evJ, s2);

    // 1a) q+k projections (o 0..1023), fused q-softmax on o0<512
    gemm_bf16<<<dim3(NN / 128, (2 * Cc) / 128, BT), 256>>>(
        wsqkv_t, xbf, nullptr, sqkv, nullptr, nullptr,
        Cc, C3, Tt, 1,
        XB, NN, TN,
        QKV_CO, QKV_CI, NN);
    cudaEventRecord(evK, 0);

    // 1b) v projection (o 1024..1535) — softmax_k overlaps this on s2
    gemm_bf16<<<dim3(NN / 128, Cc / 128, BT), 256>>>(
        wsqkv_t + 2 * Cc, xbf, nullptr, sqkv + (ll)(2 * Cc) * NN, nullptr, nullptr,
        Cc, C3, Tt, 0,
        XB, NN, TN,
        QKV_CO, QKV_CI, NN);

    // 2) k softmax on s2, concurrent with v projection
    cudaStreamWaitEvent(s2, evK, 0);
    softmax_k<<<dim3(Cc, BT), 256, 0, s2>>>(sqkv);
    cudaEventRecord(evS, s2);

    // 3) ctx (needs k-softmax [s2] + v [program order])
    cudaStreamWaitEvent(0, evS, 0);
    ctx_mma<<<dim3(HEADS, BT), 128>>>(sqkv, ctx_ed);

    // 4) apply -> sattn bf16 [bt][c][n]
    attn_apply_mma<<<dim3(NN / 256, HEADS, BT), 256>>>(ctx_ed, sqkv, sattn_bf);

    // join: wcomb/bcomb ready before GEMM5
    cudaStreamWaitEvent(0, evJ, 0);

    // 5) fused temporal qkv
    gemm_bf16<<<dim3(NN / 128, C3 / 128, BT), 256>>>(
        wcomb, sattn_bf, nullptr, tqkv, bcomb, nullptr,
        Cc, C3, Tt, 0,
        (ll)Tt * Cc * NN, (ll)Cc * NN, NN,
        (ll)C3 * TN, NN, TN);

    // 6) fused temporal attention
    temporal_fused<<<dim3(NN / ST, HEADS, Bb), 256, TSMEM>>>(tqkv, tout_bf);

    // 7) temporal proj + residual -> out fp32
    gemm_bf16<<<dim3((int)(TN / 128), Cc / 128, Bb), 256>>>(
        wtout_t, tout_bf, out, nullptr, nullptr, x,
        Cc, Cc, 1, 0,
        XB, 0, TN,
        XB, 0, TN);
}

// round 17
// speedup vs baseline: 1.0452x; 1.0313x over previous
#include <cuda_runtime.h>
#include <cuda_bf16.h>
#include <math.h>
#include <stdint.h>

#define Bb 2
#define Cc 512
#define Tt 16
#define NN 1024
#define HEADS 8
#define Dd 64
#define BT 32
#define C3 1536

typedef __nv_bfloat16 bf16;
typedef long long ll;

// ---------------- scratch (device globals) ----------------
__device__ __align__(16) bf16  g_wsqkv_t[Cc * C3];
__device__ __align__(16) bf16  g_wsout_c[Cc * Cc];
__device__ __align__(16) bf16  g_wtqkv_t[Cc * C3];
__device__ __align__(16) bf16  g_wtout_t[Cc * Cc];
__device__ __align__(16) bf16  g_wcomb[Cc * C3];
__device__ __align__(16) float g_bcomb[C3];
__device__ __align__(16) bf16  g_xbf[Bb * Cc * Tt * NN];
__device__ __align__(16) bf16  g_sqkv[BT * C3 * NN];
__device__ __align__(16) float g_ctxp[2][BT * HEADS * Dd * Dd];  // split-K partials
__device__ __align__(16) bf16  g_ctx_ed[BT * HEADS * Dd * Dd];
__device__ __align__(16) bf16  g_sattn_bf[BT * Cc * NN];
__device__ __align__(16) bf16  g_tqkv[Bb * C3 * Tt * NN];
__device__ __align__(16) bf16  g_tout_bf[Bb * Cc * Tt * NN];

// ---------------- helpers ----------------
__device__ __forceinline__ uint32_t smem_u32(const void* p) {
    uint32_t a;
    asm("{ .reg .u64 t; cvta.to.shared.u64 t, %1; cvt.u32.u64 %0, t; }" : "=r"(a) : "l"(p));
    return a;
}
#define CP_ASYNC(dst, src) asm volatile("cp.async.cg.shared.global [%0],[%1],16;\n" :: "r"(dst), "l"(src) : "memory")
#define CP_COMMIT()        asm volatile("cp.async.commit_group;\n" ::: "memory")
#define CP_WAIT0()         asm volatile("cp.async.wait_group 0;\n" ::: "memory")
#define CP_WAIT1()         asm volatile("cp.async.wait_group 1;\n" ::: "memory")
#define CP_WAIT2()         asm volatile("cp.async.wait_group 2;\n" ::: "memory")

#define LDSM_X4(r0,r1,r2,r3,addr) \
    asm volatile("ldmatrix.sync.aligned.m8n8.x4.shared.b16 {%0,%1,%2,%3},[%4];" \
                 : "=r"(r0),"=r"(r1),"=r"(r2),"=r"(r3) : "r"(addr))
#define LDSM_X4T(r0,r1,r2,r3,addr) \
    asm volatile("ldmatrix.sync.aligned.m8n8.x4.trans.shared.b16 {%0,%1,%2,%3},[%4];" \
                 : "=r"(r0),"=r"(r1),"=r"(r2),"=r"(r3) : "r"(addr))
#define LDSM_X2T(r0,r1,addr) \
    asm volatile("ldmatrix.sync.aligned.m8n8.x2.trans.shared.b16 {%0,%1},[%2];" \
                 : "=r"(r0),"=r"(r1) : "r"(addr))
#define MMA16816(d0,d1,d2,d3,a0,a1,a2,a3,b0,b1) \
    asm volatile("mma.sync.aligned.m16n8k16.row.col.f32.bf16.bf16.f32 " \
                 "{%0,%1,%2,%3},{%4,%5,%6,%7},{%8,%9},{%0,%1,%2,%3};" \
                 : "+f"(d0),"+f"(d1),"+f"(d2),"+f"(d3) \
                 : "r"(a0),"r"(a1),"r"(a2),"r"(a3),"r"(b0),"r"(b1))

// ---------------- merged prep ----------------
#define F2B_BLOCKS  16384
#define CONV_BLOCKS 8192
#define PREP_BLOCKS (F2B_BLOCKS + CONV_BLOCKS + 192)

__global__ __launch_bounds__(256) void prep_all(
    const float* __restrict__ x,
    const float* __restrict__ w1, const float* __restrict__ w2,
    const float* __restrict__ w3, const float* __restrict__ w4,
    const float* __restrict__ b_sout,
    bf16* __restrict__ xbf,
    bf16* __restrict__ o1, bf16* __restrict__ o2,
    bf16* __restrict__ o3, bf16* __restrict__ o4,
    float* __restrict__ bcomb)
{
    int blk = blockIdx.x;
    int tid = threadIdx.x;
    if (blk < F2B_BLOCKS) {
        int i = (blk * 256 + tid) * 4;
        float4 v = *(const float4*)(x + i);
        __nv_bfloat162 p0 = __floats2bfloat162_rn(v.x, v.y);
        __nv_bfloat162 p1 = __floats2bfloat162_rn(v.z, v.w);
        uint2 u;
        u.x = *(uint32_t*)&p0;
        u.y = *(uint32_t*)&p1;
        *(uint2*)(xbf + i) = u;
    } else if (blk < F2B_BLOCKS + CONV_BLOCKS) {
        const int N1 = C3 * Cc, N2 = Cc * Cc;
        int idx = (blk - F2B_BLOCKS) * 256 + tid;
        if (idx < N1) {
            int o = idx % C3, k = idx / C3;
            o1[idx] = __float2bfloat16(w1[(ll)o * Cc + k]);
        } else if (idx < N1 + N2) {
            int rem = idx - N1;
            o2[rem] = __float2bfloat16(w2[rem]);
        } else if (idx < 2 * N1 + N2) {
            int rem = idx - N1 - N2;
            int o = rem % C3, k = rem / C3;
            o3[rem] = __float2bfloat16(w3[(ll)o * Cc + k]);
        } else {
            int rem = idx - 2 * N1 - N2;
            int o = rem % Cc, k = rem / Cc;
            o4[rem] = __float2bfloat16(w4[(ll)o * Cc + k]);
        }
    } else {
        int p = (blk - F2B_BLOCKS - CONV_BLOCKS) * 8 + (tid >> 5);
        int lane = tid & 31;
        if (p >= C3) return;
        const float* wr = w3 + (ll)p * Cc;
        float s = 0.f;
        for (int o = lane; o < Cc; o += 32) s += wr[o] * b_sout[o];
        #pragma unroll
        for (int off = 16; off; off >>= 1) s += __shfl_xor_sync(0xffffffffu, s, off);
        if (lane == 0) bcomb[p] = s;
    }
}

// ---------------- bf16 tensor-core GEMM (128x128x32, 4-stage, optional fused q-softmax) ----------------
#define GST 16384
#define GSMEM (4 * GST)

__global__ __launch_bounds__(256, 2) void gemm_bf16(
    const bf16* __restrict__ Wt,   // [K][ldA]
    const bf16* __restrict__ X,
    float* __restrict__ Cf,
    bf16* __restrict__ Cb,
    const float* __restrict__ bias,
    const float* __restrict__ res,
    int K, int ldA, int gDiv, int qsmax,
    ll xOuter, ll xInner, ll xRow,
    ll cOuter, ll cInner, ll cRow)
{
    extern __shared__ bf16 gsm[];
    uint32_t sb = smem_u32(gsm);

    int g = blockIdx.z;
    ll gq = g / gDiv, gr = g % gDiv;
    const bf16* Xb = X + gq * xOuter + gr * xInner;
    ll cbase = gq * cOuter + gr * cInner;

    int n0 = blockIdx.x * 128;
    int o0 = blockIdx.y * 128;

    int tid = threadIdx.x;
    int lane = tid & 31, warp = tid >> 5;
    int wm = warp >> 2, wn = warp & 3;

    float acc[4][4][4];
    #pragma unroll
    for (int a = 0; a < 4; a++)
        #pragma unroll
        for (int b = 0; b < 4; b++)
            #pragma unroll
            for (int c = 0; c < 4; c++) acc[a][b][c] = 0.f;

    int nkt = K / 32;

    #define ISSUE_TILE(kt, buf) do {                                                   \
        int k0_ = (kt) * 32;                                                           \
        uint32_t ab_ = sb + (buf) * GST;                                               \
        uint32_t bb_ = ab_ + 8192;                                                     \
        _Pragma("unroll")                                                              \
        for (int i_ = 0; i_ < 2; i_++) {                                               \
            int idx_ = tid + 256 * i_;                                                 \
            int row_ = idx_ >> 4, ch_ = idx_ & 15;                                     \
            const bf16* sA = Wt + (ll)(k0_ + row_) * ldA + o0 + ch_ * 8;               \
            uint32_t dA = ab_ + row_ * 256 + (((ch_) ^ (row_ & 7)) << 4);              \
            CP_ASYNC(dA, sA);                                                          \
            const bf16* sB = Xb + (ll)(k0_ + row_) * xRow + n0 + ch_ * 8;              \
            uint32_t dB = bb_ + row_ * 256 + (((ch_) ^ (row_ & 7)) << 4);              \
            CP_ASYNC(dB, sB);                                                          \
        }                                                                              \
    } while (0)

    ISSUE_TILE(0, 0);
    CP_COMMIT();
    ISSUE_TILE(1, 1);
    CP_COMMIT();
    ISSUE_TILE(2, 2);
    CP_COMMIT();

    int r7 = lane & 7, sub = lane >> 3;
    int brow_lo = lane & 15;

    for (int kt = 0; kt < nkt; kt++) {
        CP_WAIT2();
        __syncthreads();
        if (kt + 3 < nkt) {
            ISSUE_TILE(kt + 3, (kt + 3) & 3);
        }
        CP_COMMIT();
        uint32_t abase = sb + (kt & 3) * GST;
        uint32_t bbase = abase + 8192;

        #pragma unroll
        for (int ks = 0; ks < 2; ks++) {
            uint32_t af[4][4];
            uint32_t bf_[4][2];
            #pragma unroll
            for (int mt = 0; mt < 4; mt++) {
                int krow = ks * 16 + r7 + ((sub >> 1) << 3);
                int mcol = wm * 64 + mt * 16 + ((sub & 1) << 3);
                uint32_t addr = abase + krow * 256 + ((((mcol >> 3)) ^ (krow & 7)) << 4);
                LDSM_X4T(af[mt][0], af[mt][1], af[mt][2], af[mt][3], addr);
            }
            #pragma unroll
            for (int nt = 0; nt < 4; nt++) {
                int brow = ks * 16 + brow_lo;
                int ncol = wn * 32 + nt * 8;
                uint32_t addr = bbase + brow * 256 + ((((ncol >> 3)) ^ (brow & 7)) << 4);
                LDSM_X2T(bf_[nt][0], bf_[nt][1], addr);
            }
            #pragma unroll
            for (int mt = 0; mt < 4; mt++)
                #pragma unroll
                for (int nt = 0; nt < 4; nt++)
                    MMA16816(acc[mt][nt][0], acc[mt][nt][1], acc[mt][nt][2], acc[mt][nt][3],
                             af[mt][0], af[mt][1], af[mt][2], af[mt][3],
                             bf_[nt][0], bf_[nt][1]);
        }
        __syncthreads();
    }

    if (qsmax && o0 < Cc) {
        #pragma unroll
        for (int nt = 0; nt < 4; nt++) {
            #pragma unroll
            for (int c = 0; c < 2; c++) {
                float m = -INFINITY;
                #pragma unroll
                for (int mt = 0; mt < 4; mt++) {
                    m = fmaxf(m, acc[mt][nt][c]);
                    m = fmaxf(m, acc[mt][nt][c + 2]);
                }
                m = fmaxf(m, __shfl_xor_sync(0xffffffffu, m, 4));
                m = fmaxf(m, __shfl_xor_sync(0xffffffffu, m, 8));
                m = fmaxf(m, __shfl_xor_sync(0xffffffffu, m, 16));
                float s = 0.f;
                #pragma unroll
                for (int mt = 0; mt < 4; mt++) {
                    acc[mt][nt][c]     = __expf(acc[mt][nt][c] - m);
                    acc[mt][nt][c + 2] = __expf(acc[mt][nt][c + 2] - m);
                    s += acc[mt][nt][c] + acc[mt][nt][c + 2];
                }
                s += __shfl_xor_sync(0xffffffffu, s, 4);
                s += __shfl_xor_sync(0xffffffffu, s, 8);
                s += __shfl_xor_sync(0xffffffffu, s, 16);
                float inv = 0.125f / s;
                #pragma unroll
                for (int mt = 0; mt < 4; mt++) {
                    acc[mt][nt][c]     *= inv;
                    acc[mt][nt][c + 2] *= inv;
                }
            }
        }
    }

    int g4 = lane >> 2, t4 = lane & 3;
    #pragma unroll
    for (int mt = 0; mt < 4; mt++) {
        #pragma unroll
        for (int nt = 0; nt < 4; nt++) {
            int orow = o0 + wm * 64 + mt * 16 + g4;
            int col  = n0 + wn * 32 + nt * 8 + t4 * 2;
            ll off0 = cbase + (ll)orow * cRow + col;
            ll off1 = off0 + 8 * cRow;
            float b0 = bias ? bias[orow] : 0.f;
            float b1 = bias ? bias[orow + 8] : 0.f;
            float* a = acc[mt][nt];
            if (Cb) {
                __nv_bfloat162 v0 = __floats2bfloat162_rn(a[0] + b0, a[1] + b0);
                __nv_bfloat162 v1 = __floats2bfloat162_rn(a[2] + b1, a[3] + b1);
                *reinterpret_cast<__nv_bfloat162*>(Cb + off0) = v0;
                *reinterpret_cast<__nv_bfloat162*>(Cb + off1) = v1;
            } else {
                float2 r0 = make_float2(0.f, 0.f), r1 = make_float2(0.f, 0.f);
                if (res) { r0 = *(const float2*)(res + off0); r1 = *(const float2*)(res + off1); }
                float2 o0v = make_float2(a[0] + b0 + r0.x, a[1] + b0 + r0.y);
                float2 o1v = make_float2(a[2] + b1 + r1.x, a[3] + b1 + r1.y);
                *(float2*)(Cf + off0) = o0v;
                *(float2*)(Cf + off1) = o1v;
            }
        }
    }
    #undef ISSUE_TILE
}

// ---------------- k softmax (over n, bf16 in/out, vectorized) ----------------
__global__ __launch_bounds__(256) void softmax_k(bf16* __restrict__ p)
{
    bf16* row = p + (ll)blockIdx.y * C3 * NN + (ll)(Cc + blockIdx.x) * NN;
    int tid = threadIdx.x;
    uint2 u = *(uint2*)(row + tid * 4);
    __nv_bfloat162 p0 = *(__nv_bfloat162*)&u.x;
    __nv_bfloat162 p1 = *(__nv_bfloat162*)&u.y;
    float v[4];
    v[0] = __bfloat162float(p0.x); v[1] = __bfloat162float(p0.y);
    v[2] = __bfloat162float(p1.x); v[3] = __bfloat162float(p1.y);
    float m = fmaxf(fmaxf(v[0], v[1]), fmaxf(v[2], v[3]));
    __shared__ float red[8];
    #pragma unroll
    for (int o = 16; o; o >>= 1) m = fmaxf(m, __shfl_xor_sync(0xffffffffu, m, o));
    if ((tid & 31) == 0) red[tid >> 5] = m;
    __syncthreads();
    m = red[0];
    #pragma unroll
    for (int wv = 1; wv < 8; wv++) m = fmaxf(m, red[wv]);
    __syncthreads();
    float s = 0.f;
    #pragma unroll
    for (int k = 0; k < 4; k++) { v[k] = __expf(v[k] - m); s += v[k]; }
    #pragma unroll
    for (int o = 16; o; o >>= 1) s += __shfl_xor_sync(0xffffffffu, s, o);
    if ((tid & 31) == 0) red[tid >> 5] = s;
    __syncthreads();
    s = 0.f;
    #pragma unroll
    for (int wv = 0; wv < 8; wv++) s += red[wv];
    float inv = 1.f / s;
    __nv_bfloat162 q0 = __floats2bfloat162_rn(v[0] * inv, v[1] * inv);
    __nv_bfloat162 q1 = __floats2bfloat162_rn(v[2] * inv, v[3] * inv);
    uint2 w;
    w.x = *(uint32_t*)&q0;
    w.y = *(uint32_t*)&q1;
    *(uint2*)(row + tid * 4) = w;
}

// ---------------- ctx split-K: partial[z][e][d] = sum_{n in half z} k[d][n] v[e][n] ----------------
__global__ __launch_bounds__(128) void ctx_mma_sk(const bf16* __restrict__ qkv,
                                                  float* __restrict__ ctxp)
{
    int h = blockIdx.x, bt = blockIdx.y, z = blockIdx.z;
    const bf16* kbase = qkv + (ll)bt * C3 * NN + (ll)(Cc + h * Dd) * NN + z * 512;
    const bf16* vbase = qkv + (ll)bt * C3 * NN + (ll)(2 * Cc + h * Dd) * NN + z * 512;

    __shared__ bf16 Ks[2][64 * 64];
    __shared__ bf16 Vs[2][64 * 64];
    uint32_t ksb = smem_u32(&Ks[0][0]);
    uint32_t vsb = smem_u32(&Vs[0][0]);

    int tid = threadIdx.x;
    int lane = tid & 31, warp = tid >> 5;
    int m0 = warp * 16;

    float acc[8][4] = {};

    #define CTX_ISSUE(c, buf) do {                                                  \
        _Pragma("unroll")                                                           \
        for (int i_ = 0; i_ < 8; i_++) {                                            \
            int idx_ = i_ * 128 + tid;                                              \
            int mat_ = idx_ >> 9;                                                   \
            int rem_ = idx_ & 511;                                                  \
            int row_ = rem_ >> 3, ch_ = rem_ & 7;                                   \
            const bf16* src_ = (mat_ ? vbase : kbase) + (ll)row_ * NN + (c) * 64 + ch_ * 8; \
            uint32_t dst_ = (mat_ ? vsb : ksb) + (buf) * 8192 + row_ * 128 + ((ch_ ^ (row_ & 7)) << 4); \
            CP_ASYNC(dst_, src_);                                                   \
        }                                                                           \
    } while (0)

    CTX_ISSUE(0, 0);
    CP_COMMIT();

    for (int c = 0; c < 8; c++) {
        CP_WAIT0();
        __syncthreads();
        if (c + 1 < 8) { CTX_ISSUE(c + 1, (c + 1) & 1); CP_COMMIT(); }
        int buf = c & 1;
        uint32_t ka = ksb + buf * 8192;
        uint32_t va = vsb + buf * 8192;
        #pragma unroll
        for (int ks = 0; ks < 4; ks++) {
            int k0 = ks * 16;
            uint32_t a0, a1, a2, a3;
            {
                int row = m0 + (lane & 15);
                int ch  = (k0 >> 3) + (lane >> 4);
                uint32_t addr = ka + row * 128 + ((ch ^ (row & 7)) << 4);
                LDSM_X4(a0, a1, a2, a3, addr);
            }
            #pragma unroll
            for (int nb = 0; nb < 4; nb++) {
                int row = nb * 16 + ((lane >> 4) << 3) + (lane & 7);
                int ch  = (k0 >> 3) + ((lane >> 3) & 1);
                uint32_t addr = va + row * 128 + ((ch ^ (row & 7)) << 4);
                uint32_t r0, r1, r2, r3;
                LDSM_X4(r0, r1, r2, r3, addr);
                MMA16816(acc[nb*2][0],   acc[nb*2][1],   acc[nb*2][2],   acc[nb*2][3],
                         a0, a1, a2, a3, r0, r1);
                MMA16816(acc[nb*2+1][0], acc[nb*2+1][1], acc[nb*2+1][2], acc[nb*2+1][3],
                         a0, a1, a2, a3, r2, r3);
            }
        }
        __syncthreads();
    }
    #undef CTX_ISSUE

    float* cb = ctxp + ((ll)z * BT * HEADS + (ll)bt * HEADS + h) * (Dd * Dd);
    int g4 = lane >> 2, t4 = lane & 3;
    #pragma unroll
    for (int nt = 0; nt < 8; nt++) {
        int e0 = nt * 8 + t4 * 2;
        int d0 = m0 + g4;
        cb[(e0)     * Dd + d0]     = acc[nt][0];
        cb[(e0 + 1) * Dd + d0]     = acc[nt][1];
        cb[(e0)     * Dd + d0 + 8] = acc[nt][2];
        cb[(e0 + 1) * Dd + d0 + 8] = acc[nt][3];
    }
}

// combine the two split-K partials -> bf16 ctx_ed
__global__ __launch_bounds__(256) void ctx_combine(const float* __restrict__ ctxp,
                                                   bf16* __restrict__ ctx_ed)
{
    const int N = BT * HEADS * Dd * Dd;
    int i = (blockIdx.x * 256 + threadIdx.x) * 4;
    if (i >= N) return;
    float4 a = *(const float4*)(ctxp + i);
    float4 b = *(const float4*)(ctxp + N + i);
    __nv_bfloat162 v0 = __floats2bfloat162_rn(a.x + b.x, a.y + b.y);
    __nv_bfloat162 v1 = __floats2bfloat162_rn(a.z + b.z, a.w + b.w);
    uint2 u;
    u.x = *(uint32_t*)&v0;
    u.y = *(uint32_t*)&v1;
    *(uint2*)(ctx_ed + i) = u;
}

// ---------------- attn apply: out[e][n] -> sattn [bt][c][n] ----------------
__global__ __launch_bounds__(256) void attn_apply_mma(const bf16* __restrict__ ctx_ed,
                                                      const bf16* __restrict__ qkv,
                                                      bf16* __restrict__ out)
{
    int n0 = blockIdx.x * 256, h = blockIdx.y, bt = blockIdx.z;
    const bf16* cbase = ctx_ed + ((ll)bt * HEADS + h) * (Dd * Dd);
    const bf16* qbase = qkv + (ll)bt * C3 * NN + (ll)(h * Dd) * NN;

    __shared__ bf16 Asm[64 * 64];
    __shared__ bf16 Bsm[64 * 256];
    uint32_t asb = smem_u32(&Asm[0]);
    uint32_t bsb = smem_u32(&Bsm[0]);

    int tid = threadIdx.x;
    int lane = tid & 31, warp = tid >> 5;
    int wm = warp >> 2, wn = warp & 3;

    #pragma unroll
    for (int i = 0; i < 2; i++) {
        int idx = i * 256 + tid;
        int row = idx >> 3, ch = idx & 7;
        const bf16* src = cbase + row * Dd + ch * 8;
        uint32_t dst = asb + row * 128 + ((ch ^ (row & 7)) << 4);
        CP_ASYNC(dst, src);
    }
    #pragma unroll
    for (int i = 0; i < 8; i++) {
        int idx = i * 256 + tid;
        int row = idx >> 5, ch = idx & 31;
        const bf16* src = qbase + (ll)row * NN + n0 + ch * 8;
        uint32_t dst = bsb + row * 512 + ((ch ^ (row & 7)) << 4);
        CP_ASYNC(dst, src);
    }
    CP_COMMIT();
    CP_WAIT0();
    __syncthreads();

    float acc[2][8][4] = {};
    #pragma unroll
    for (int ks = 0; ks < 4; ks++) {
        int k0 = ks * 16;
        uint32_t af[2][4];
        #pragma unroll
        for (int mt = 0; mt < 2; mt++) {
            int row = wm * 32 + mt * 16 + (lane & 15);
            int ch  = (k0 >> 3) + (lane >> 4);
            uint32_t addr = asb + row * 128 + ((ch ^ (row & 7)) << 4);
            LDSM_X4(af[mt][0], af[mt][1], af[mt][2], af[mt][3], addr);
        }
        #pragma unroll
        for (int nt = 0; nt < 8; nt++) {
            int krow = k0 + (lane & 15);
            int ncol = wn * 64 + nt * 8;
            uint32_t addr = bsb + krow * 512 + (((ncol >> 3) ^ (krow & 7)) << 4);
            uint32_t b0, b1;
            LDSM_X2T(b0, b1, addr);
            #pragma unroll
            for (int mt = 0; mt < 2; mt++)
                MMA16816(acc[mt][nt][0], acc[mt][nt][1], acc[mt][nt][2], acc[mt][nt][3],
                         af[mt][0], af[mt][1], af[mt][2], af[mt][3], b0, b1);
        }
    }

    bf16* ob = out + (ll)bt * Cc * NN + (ll)(h * Dd) * NN;
    int g4 = lane >> 2, t4 = lane & 3;
    #pragma unroll
    for (int mt = 0; mt < 2; mt++) {
        #pragma unroll
        for (int nt = 0; nt < 8; nt++) {
            int erow = wm * 32 + mt * 16 + g4;
            int col  = n0 + wn * 64 + nt * 8 + t4 * 2;
            float* a = acc[mt][nt];
            __nv_bfloat162 v0 = __floats2bfloat162_rn(a[0], a[1]);
            __nv_bfloat162 v1 = __floats2bfloat162_rn(a[2], a[3]);
            *reinterpret_cast<__nv_bfloat162*>(ob + (ll)erow * NN + col) = v0;
            *reinterpret_cast<__nv_bfloat162*>(ob + (ll)(erow + 8) * NN + col) = v1;
        }
    }
}

// ---------------- fused temporal attention (ST=16, 256 threads, bf16 smem) ----------------
#define ST 16
#define TSMEM (2 * 1024 * 16 * 2 + 256 * 16 * 4)   // 98304 B

__global__ __launch_bounds__(256) void temporal_fused(const bf16* __restrict__ tqkv,
                                                      bf16* __restrict__ out)
{
    extern __shared__ char tsm2[];
    bf16*  ks   = (bf16*)tsm2;
    bf16*  vs   = ks + 1024 * 16;
    float* attw = (float*)(vs + 1024 * 16);

    int b = blockIdx.z, hh = blockIdx.y;
    int s0 = blockIdx.x * ST;
    const ll TN = (ll)Tt * NN;
    const bf16* kb = tqkv + ((ll)b * C3 + Cc + hh * Dd) * TN;
    const bf16* vb = tqkv + ((ll)b * C3 + 2 * Cc + hh * Dd) * TN;
    int tid = threadIdx.x;

    #pragma unroll
    for (int l = 0; l < 16; l++) {
        int idx = l * 256 + tid;
        int arr = idx >> 11;
        int rem = idx & 2047;
        int row = rem >> 1, ch = rem & 1;
        int d = row & 63, j = row >> 6;
        const bf16* src = (arr ? vb : kb) + (ll)d * TN + j * NN + s0 + ch * 8;
        bf16* dst = (arr ? vs : ks) + row * 16 + ch * 8;
        *(uint4*)dst = *(const uint4*)src;
    }
    __syncthreads();

    int sl = tid & 15;
    int i  = tid >> 4;

    {
        const bf16* qb = tqkv + ((ll)b * C3 + hh * Dd) * TN + (ll)i * NN + s0 + sl;
        float acc[16];
        #pragma unroll
        for (int j = 0; j < 16; j++) acc[j] = 0.f;
        for (int d = 0; d < 64; d++) {
            float qv = __bfloat162float(qb[(ll)d * TN]) * 0.125f;
            #pragma unroll
            for (int j = 0; j < 16; j++)
                acc[j] += qv * __bfloat162float(ks[(j * 64 + d) * 16 + sl]);
        }
        float m = acc[0];
        #pragma unroll
        for (int j = 1; j < 16; j++) m = fmaxf(m, acc[j]);
        float sum = 0.f;
        #pragma unroll
        for (int j = 0; j < 16; j++) { acc[j] = __expf(acc[j] - m); sum += acc[j]; }
        float inv = 1.f / sum;
        #pragma unroll
        for (int j = 0; j < 16; j++)
            attw[(i * 16 + j) * 16 + sl] = acc[j] * inv;
    }
    __syncthreads();

    int dg = i;
    bf16* ob = out + ((ll)b * Cc + hh * Dd + dg * 4) * TN + s0 + sl;
    for (int ii = 0; ii < 16; ii++) {
        float a0 = 0.f, a1 = 0.f, a2 = 0.f, a3 = 0.f;
        #pragma unroll
        for (int j = 0; j < 16; j++) {
            float av = attw[(ii * 16 + j) * 16 + sl];
            a0 += av * __bfloat162float(vs[(j * 64 + dg * 4 + 0) * 16 + sl]);
            a1 += av * __bfloat162float(vs[(j * 64 + dg * 4 + 1) * 16 + sl]);
            a2 += av * __bfloat162float(vs[(j * 64 + dg * 4 + 2) * 16 + sl]);
            a3 += av * __bfloat162float(vs[(j * 64 + dg * 4 + 3) * 16 + sl]);
        }
        ll t_off = (ll)ii * NN;
        ob[t_off + 0 * TN] = __float2bfloat16(a0);
        ob[t_off + 1 * TN] = __float2bfloat16(a1);
        ob[t_off + 2 * TN] = __float2bfloat16(a2);
        ob[t_off + 3 * TN] = __float2bfloat16(a3);
    }
}

// ---------------- launch ----------------
extern "C" void kernel_launch(void* const* d_in, const int* in_sizes, int n_in,
                              void* d_out, int out_size)
{
    const float* x      = (const float*)d_in[0];
    const float* w_sqkv = (const float*)d_in[1];
    const float* w_sout = (const float*)d_in[2];
    const float* b_sout = (const float*)d_in[3];
    const float* w_tqkv = (const float*)d_in[4];
    const float* w_tout = (const float*)d_in[5];
    float* out = (float*)d_out;

    bf16 *wsqkv_t, *wsout_c, *wtqkv_t, *wtout_t, *wcomb, *xbf, *sqkv, *ctx_ed, *sattn_bf, *tqkv, *tout_bf;
    float *bcomb, *ctxp;
    cudaGetSymbolAddress((void**)&wsqkv_t, g_wsqkv_t);
    cudaGetSymbolAddress((void**)&wsout_c, g_wsout_c);
    cudaGetSymbolAddress((void**)&wtqkv_t, g_wtqkv_t);
    cudaGetSymbolAddress((void**)&wtout_t, g_wtout_t);
    cudaGetSymbolAddress((void**)&wcomb,   g_wcomb);
    cudaGetSymbolAddress((void**)&bcomb,   g_bcomb);
    cudaGetSymbolAddress((void**)&xbf,     g_xbf);
    cudaGetSymbolAddress((void**)&sqkv,    g_sqkv);
    cudaGetSymbolAddress((void**)&ctxp,    g_ctxp);
    cudaGetSymbolAddress((void**)&ctx_ed,  g_ctx_ed);
    cudaGetSymbolAddress((void**)&sattn_bf,g_sattn_bf);
    cudaGetSymbolAddress((void**)&tqkv,    g_tqkv);
    cudaGetSymbolAddress((void**)&tout_bf, g_tout_bf);

    static int attr_set = 0;
    static cudaStream_t s2;
    static cudaEvent_t evF, evJ, evK, evS;
    if (!attr_set) {
        cudaFuncSetAttribute(temporal_fused, cudaFuncAttributeMaxDynamicSharedMemorySize, TSMEM);
        cudaFuncSetAttribute(gemm_bf16, cudaFuncAttributeMaxDynamicSharedMemorySize, GSMEM);
        cudaStreamCreateWithFlags(&s2, cudaStreamNonBlocking);
        cudaEventCreateWithFlags(&evF, cudaEventDisableTiming);
        cudaEventCreateWithFlags(&evJ, cudaEventDisableTiming);
        cudaEventCreateWithFlags(&evK, cudaEventDisableTiming);
        cudaEventCreateWithFlags(&evS, cudaEventDisableTiming);
        attr_set = 1;
    }

    const ll TN = (ll)Tt * NN;
    const ll XB = (ll)Cc * TN;
    const ll QKV_CO = (ll)Tt * C3 * NN;
    const ll QKV_CI = (ll)C3 * NN;

    // 0) merged prep
    prep_all<<<PREP_BLOCKS, 256>>>(x, w_sqkv, w_sout, w_tqkv, w_tout, b_sout,
                                   xbf, wsqkv_t, wsout_c, wtqkv_t, wtout_t, bcomb);

    // fork: combine GEMM on s2
    cudaEventRecord(evF, 0);
    cudaStreamWaitEvent(s2, evF, 0);
    gemm_bf16<<<dim3(C3 / 128, Cc / 128, 1), 256, GSMEM, s2>>>(
        wsout_c, wtqkv_t, nullptr, wcomb, nullptr, nullptr,
        Cc, Cc, 1, 0,
        0, 0, C3,
        0, 0, C3);
    cudaEventRecord(evJ, s2);

    // 1a) q+k projections (o 0..1023), fused q-softmax on o0<512
    gemm_bf16<<<dim3(NN / 128, (2 * Cc) / 128, BT), 256, GSMEM>>>(
        wsqkv_t, xbf, nullptr, sqkv, nullptr, nullptr,
        Cc, C3, Tt, 1,
        XB, NN, TN,
        QKV_CO, QKV_CI, NN);
    cudaEventRecord(evK, 0);

    // 1b) v projection (o 1024..1535) — softmax_k overlaps this on s2
    gemm_bf16<<<dim3(NN / 128, Cc / 128, BT), 256, GSMEM>>>(
        wsqkv_t + 2 * Cc, xbf, nullptr, sqkv + (ll)(2 * Cc) * NN, nullptr, nullptr,
        Cc, C3, Tt, 0,
        XB, NN, TN,
        QKV_CO, QKV_CI, NN);

    // 2) k softmax on s2, concurrent with v projection
    cudaStreamWaitEvent(s2, evK, 0);
    softmax_k<<<dim3(Cc, BT), 256, 0, s2>>>(sqkv);
    cudaEventRecord(evS, s2);

    // 3) ctx split-K + combine
    cudaStreamWaitEvent(0, evS, 0);
    ctx_mma_sk<<<dim3(HEADS, BT, 2), 128>>>(sqkv, ctxp);
    ctx_combine<<<(BT * HEADS * Dd * Dd / 4 + 255) / 256, 256>>>(ctxp, ctx_ed);

    // 4) apply -> sattn bf16 [bt][c][n]
    attn_apply_mma<<<dim3(NN / 256, HEADS, BT), 256>>>(ctx_ed, sqkv, sattn_bf);

    // join: wcomb/bcomb ready before GEMM5
    cudaStreamWaitEvent(0, evJ, 0);

    // 5) fused temporal qkv
    gemm_bf16<<<dim3(NN / 128, C3 / 128, BT), 256, GSMEM>>>(
        wcomb, sattn_bf, nullptr, tqkv, bcomb, nullptr,
        Cc, C3, Tt, 0,
        (ll)Tt * Cc * NN, (ll)Cc * NN, NN,
        (ll)C3 * TN, NN, TN);

    // 6) fused temporal attention
    temporal_fused<<<dim3(NN / ST, HEADS, Bb), 256, TSMEM>>>(tqkv, tout_bf);

    // 7) temporal proj + residual -> out fp32
    gemm_bf16<<<dim3((int)(TN / 128), Cc / 128, Bb), 256, GSMEM>>>(
        wtout_t, tout_bf, out, nullptr, nullptr, x,
        Cc, Cc, 1, 0,
        XB, 0, TN,
        XB, 0, TN);
}